// round 12
// baseline (speedup 1.0000x reference)
#include <cuda_runtime.h>
#include <cuda_fp16.h>
#include <cstdint>
#include <cstddef>

// Problem constants
#define Bc  16
#define Sc  512
#define Dc  1024
#define Hc  16
#define DKc 64
#define Mc  8192   // B*S
#define Gc  8192   // H*S

#define OUT_ELEMS  8388608LL
#define ATTN_ELEMS 67108864LL

// -------------------- device scratch (static globals; no allocs) -----------
__device__ __half g_gt [(size_t)Mc * Gc];     // gate [b*S+s][h*S+k] fp16
__device__ __half g_ah[(size_t)Mc * Dc];      // activation hi / later ctx hi
__device__ __half g_al[(size_t)Mc * Dc];      // activation lo / later ctx lo
__device__ __half g_wh[(size_t)Gc * Dc];      // weight^T hi [N,K]
__device__ __half g_wl[(size_t)Gc * Dc];      // weight^T lo
__device__ __half g_qh[(size_t)Mc * Dc];
__device__ __half g_ql[(size_t)Mc * Dc];
__device__ __half g_kh[(size_t)Mc * Dc];
__device__ __half g_kl[(size_t)Mc * Dc];
__device__ __half g_vh[(size_t)Mc * Dc];
// softmax partial stats: per (b*H+h, 64-col slot 0..7, row 0..511)
__device__ float g_pm[(size_t)Bc * Hc * 8 * Sc];
__device__ float g_ps[(size_t)Bc * Hc * 8 * Sc];

// ===================== PTX helpers (sm_80-level only) ======================
__device__ __forceinline__ uint32_t smem_u32(const void* p) {
    uint32_t a;
    asm("{ .reg .u64 t; cvta.to.shared.u64 t, %1; cvt.u32.u64 %0, t; }" : "=r"(a) : "l"(p));
    return a;
}
__device__ __forceinline__ void cp16(uint32_t smem, const void* g) {
    asm volatile("cp.async.cg.shared.global [%0], [%1], 16;\n" :: "r"(smem), "l"(g));
}
#define CP_COMMIT() asm volatile("cp.async.commit_group;" ::: "memory")
#define CP_WAIT0()  asm volatile("cp.async.wait_group 0;" ::: "memory")

#define LDSM4(r0, r1, r2, r3, addr) \
    asm volatile("ldmatrix.sync.aligned.m8n8.x4.shared.b16 {%0,%1,%2,%3}, [%4];" \
        : "=r"(r0), "=r"(r1), "=r"(r2), "=r"(r3) : "r"(addr))
#define LDSM4T(r0, r1, r2, r3, addr) \
    asm volatile("ldmatrix.sync.aligned.m8n8.x4.trans.shared.b16 {%0,%1,%2,%3}, [%4];" \
        : "=r"(r0), "=r"(r1), "=r"(r2), "=r"(r3) : "r"(addr))

#define MMA_F16(d, a, b) \
    asm volatile("mma.sync.aligned.m16n8k16.row.col.f32.f16.f16.f32 " \
        "{%0,%1,%2,%3},{%4,%5,%6,%7},{%8,%9},{%0,%1,%2,%3};" \
        : "+f"((d)[0]), "+f"((d)[1]), "+f"((d)[2]), "+f"((d)[3]) \
        : "r"((a)[0]), "r"((a)[1]), "r"((a)[2]), "r"((a)[3]), \
          "r"((b)[0]), "r"((b)[1]))

// ===================== conversion kernels ==================================
__global__ void __launch_bounds__(256)
split_kernel(const float* __restrict__ x, __half* __restrict__ hi,
             __half* __restrict__ lo, long long n4)
{
    long long i = ((long long)blockIdx.x * 256 + threadIdx.x);
    if (i >= n4) return;
    const float4 v = ((const float4*)x)[i];
    const __half h0 = __float2half_rn(v.x);
    const __half h1 = __float2half_rn(v.y);
    const __half h2 = __float2half_rn(v.z);
    const __half h3 = __float2half_rn(v.w);
    ((__half2*)hi)[i * 2 + 0] = __halves2half2(h0, h1);
    ((__half2*)hi)[i * 2 + 1] = __halves2half2(h2, h3);
    ((__half2*)lo)[i * 2 + 0] = __halves2half2(
        __float2half_rn(v.x - __half2float(h0)),
        __float2half_rn(v.y - __half2float(h1)));
    ((__half2*)lo)[i * 2 + 1] = __halves2half2(
        __float2half_rn(v.z - __half2float(h2)),
        __float2half_rn(v.w - __half2float(h3)));
}

// W[K][N] fp32 -> T[N][K] fp16 hi/lo
__global__ void __launch_bounds__(256)
transpose_split(const float* __restrict__ W, __half* __restrict__ Th,
                __half* __restrict__ Tl, int K, int N)
{
    __shared__ float t[32][33];
    const int n0 = blockIdx.x * 32, k0 = blockIdx.y * 32;
    const int tx = threadIdx.x, ty = threadIdx.y;  // (32, 8)
    #pragma unroll
    for (int p = 0; p < 4; p++) {
        const int kk = ty + p * 8;
        t[kk][tx] = W[(size_t)(k0 + kk) * N + n0 + tx];
    }
    __syncthreads();
    #pragma unroll
    for (int p = 0; p < 4; p++) {
        const int nn = ty + p * 8;
        const float v = t[tx][nn];
        const __half h = __float2half_rn(v);
        Th[(size_t)(n0 + nn) * K + k0 + tx] = h;
        Tl[(size_t)(n0 + nn) * K + k0 + tx] = __float2half_rn(v - __half2float(h));
    }
}

// ===================== mma.sync split-fp16 GEMM ============================
// PASSES==3: Ah@Bh + Ah@Bl + Al@Bh.  PASSES==2: Ah@Bh + Al@Bh.  PASSES==1: Ah@Bh.
// MODE 0: C fp32 (+bias). MODE 1: fp16 hi/lo split. MODE 2: fp16 hi only.
#define RS 80
#define TILE_B   (128 * RS)
#define STAGE_B  (4 * TILE_B)
#define GEMM_SMEM (2 * STAGE_B)      // 81920

template<int MODE, int PASSES>
__global__ void __launch_bounds__(256, 2)
gemm_mma(const __half* __restrict__ Ah, const __half* __restrict__ Al,
         const __half* __restrict__ Bh, const __half* __restrict__ Bl,
         const float* __restrict__ bias, float* __restrict__ C,
         __half* __restrict__ Ch, __half* __restrict__ Cl,
         int Ntot, int K)
{
    extern __shared__ char dsm[];
    const uint32_t sb0 = smem_u32(dsm);
    const int tid  = threadIdx.x;
    const int lane = tid & 31;
    const int wid  = tid >> 5;
    const int wm   = wid & 3;
    const int wn   = wid >> 2;
    const int m0   = blockIdx.y * 128;
    const int n0   = blockIdx.x * 128;

    const size_t Kb = (size_t)K * 2;
    const int NK = K >> 5;

    const char* pAh = (const char*)Ah + (size_t)m0 * Kb;
    const char* pAl = (const char*)Al + (size_t)m0 * Kb;
    const char* pBh = (const char*)Bh + (size_t)n0 * Kb;
    const char* pBl = (const char*)Bl + (size_t)n0 * Kb;

    auto load_stage = [&](int kt, int s) {
        const uint32_t sb = sb0 + (uint32_t)s * STAGE_B;
        const size_t kb = (size_t)kt * 64;
        #pragma unroll
        for (int i = 0; i < 2; i++) {
            const int c   = tid + i * 256;
            const int row = c >> 2;
            const int seg = (c & 3) * 16;
            const uint32_t so = (uint32_t)(row * RS + seg);
            const size_t go = (size_t)row * Kb + kb + seg;
            cp16(sb + so, pAh + go);
            if (PASSES >= 2) cp16(sb + TILE_B + so, pAl + go);
            cp16(sb + 2 * TILE_B + so, pBh + go);
            if (PASSES == 3) cp16(sb + 3 * TILE_B + so, pBl + go);
        }
    };

    const uint32_t aRow  = (uint32_t)(wm * 32 + (lane & 15));
    const uint32_t aByte = (uint32_t)((lane >> 4) * 16);
    const uint32_t bRow  = (uint32_t)(wn * 64 + (lane & 7) + ((lane >> 4) & 1) * 8);
    const uint32_t bByte = (uint32_t)(((lane >> 3) & 1) * 16);

    float acc[2][8][4] = {};

    load_stage(0, 0); CP_COMMIT();

    for (int kt = 0; kt < NK; kt++) {
        const int s = kt & 1;
        CP_WAIT0();
        __syncthreads();
        if (kt + 1 < NK) { load_stage(kt + 1, s ^ 1); CP_COMMIT(); }

        const uint32_t sb = sb0 + (uint32_t)s * STAGE_B;

        #pragma unroll
        for (int kk = 0; kk < 2; kk++) {
            uint32_t ah[2][4], al[2][4];
            #pragma unroll
            for (int mi = 0; mi < 2; mi++) {
                const uint32_t ad = sb + (aRow + mi * 16) * RS + kk * 32 + aByte;
                LDSM4(ah[mi][0], ah[mi][1], ah[mi][2], ah[mi][3], ad);
                if (PASSES >= 2)
                    LDSM4(al[mi][0], al[mi][1], al[mi][2], al[mi][3], ad + TILE_B);
            }
            #pragma unroll
            for (int hf = 0; hf < 2; hf++) {
                uint32_t bh[4][2], bl[4][2];
                #pragma unroll
                for (int p = 0; p < 2; p++) {
                    const uint32_t bd = sb + 2 * TILE_B +
                        (bRow + (hf * 2 + p) * 16) * RS + kk * 32 + bByte;
                    uint32_t t0, t1, t2, t3;
                    LDSM4(t0, t1, t2, t3, bd);
                    bh[2 * p][0] = t0; bh[2 * p][1] = t1;
                    bh[2 * p + 1][0] = t2; bh[2 * p + 1][1] = t3;
                    if (PASSES == 3) {
                        LDSM4(t0, t1, t2, t3, bd + TILE_B);
                        bl[2 * p][0] = t0; bl[2 * p][1] = t1;
                        bl[2 * p + 1][0] = t2; bl[2 * p + 1][1] = t3;
                    }
                }
                #pragma unroll
                for (int mi = 0; mi < 2; mi++)
                    #pragma unroll
                    for (int nj = 0; nj < 4; nj++) {
                        float* d = acc[mi][hf * 4 + nj];
                        MMA_F16(d, ah[mi], bh[nj]);
                        if (PASSES == 3) MMA_F16(d, ah[mi], bl[nj]);
                        if (PASSES >= 2) MMA_F16(d, al[mi], bh[nj]);
                    }
            }
        }
    }

    const int trow = lane >> 2;
    const int tc   = (lane & 3) * 2;
    #pragma unroll
    for (int mi = 0; mi < 2; mi++) {
        const int r = m0 + wm * 32 + mi * 16 + trow;
        #pragma unroll
        for (int ni = 0; ni < 8; ni++) {
            const int col = n0 + wn * 64 + ni * 8 + tc;
            const float2 bv = *(const float2*)(bias + col);
            const float v00 = acc[mi][ni][0] + bv.x;
            const float v01 = acc[mi][ni][1] + bv.y;
            const float v10 = acc[mi][ni][2] + bv.x;
            const float v11 = acc[mi][ni][3] + bv.y;
            if (MODE == 0) {
                float2 o0 = {v00, v01}, o1 = {v10, v11};
                *(float2*)(C + (size_t)r * Ntot + col) = o0;
                *(float2*)(C + (size_t)(r + 8) * Ntot + col) = o1;
            } else if (MODE == 1) {
                const __half h00 = __float2half_rn(v00);
                const __half h01 = __float2half_rn(v01);
                const __half h10 = __float2half_rn(v10);
                const __half h11 = __float2half_rn(v11);
                *(__half2*)(Ch + (size_t)r * Ntot + col) = __halves2half2(h00, h01);
                *(__half2*)(Cl + (size_t)r * Ntot + col) = __halves2half2(
                    __float2half_rn(v00 - __half2float(h00)),
                    __float2half_rn(v01 - __half2float(h01)));
                *(__half2*)(Ch + (size_t)(r + 8) * Ntot + col) = __halves2half2(h10, h11);
                *(__half2*)(Cl + (size_t)(r + 8) * Ntot + col) = __halves2half2(
                    __float2half_rn(v10 - __half2float(h10)),
                    __float2half_rn(v11 - __half2float(h11)));
            } else {  // MODE 2: fp16 hi only
                *(__half2*)(Ch + (size_t)r * Ntot + col) =
                    __halves2half2(__float2half_rn(v00), __float2half_rn(v01));
                *(__half2*)(Ch + (size_t)(r + 8) * Ntot + col) =
                    __halves2half2(__float2half_rn(v10), __float2half_rn(v11));
            }
        }
    }
}

// ===================== scores via mma + softmax partial stats ==============
// grid (4, 4, 256): 128x128 tile per (b,h). Epilogue also writes per-row
// (max, exp-sum) partials for its 64-col warp slice (slot = bx*2 + wn).
#define RS2 144
#define SC_TILE (128 * RS2)
#define SC_SMEM (4 * SC_TILE)         // 73728: Qh | Ql | Kh | Kl

__global__ void __launch_bounds__(256, 2)
scores_tc(const float* __restrict__ prev, const float* __restrict__ scale_p,
          float* __restrict__ scores)
{
    extern __shared__ char dsm[];
    const uint32_t sb = smem_u32(dsm);
    const int tid  = threadIdx.x;
    const int lane = tid & 31;
    const int wid  = tid >> 5;
    const int wm   = wid & 3;
    const int wn   = wid >> 2;
    const int bh = blockIdx.z;
    const int b  = bh >> 4;
    const int h  = bh & 15;
    const int q0 = blockIdx.y * 128;
    const int n0 = blockIdx.x * 128;

    const char* pQh = (const char*)g_qh + ((size_t)(b * Sc + q0) * Dc + h * DKc) * 2;
    const char* pQl = (const char*)g_ql + ((size_t)(b * Sc + q0) * Dc + h * DKc) * 2;
    const char* pKh = (const char*)g_kh + ((size_t)(b * Sc + n0) * Dc + h * DKc) * 2;
    const char* pKl = (const char*)g_kl + ((size_t)(b * Sc + n0) * Dc + h * DKc) * 2;
    #pragma unroll
    for (int i = 0; i < 4; i++) {
        const int c   = tid + i * 256;
        const int row = c >> 3;
        const int seg = (c & 7) * 16;
        const uint32_t so = (uint32_t)(row * RS2 + seg);
        const size_t go = (size_t)row * (Dc * 2) + seg;
        cp16(sb + so,               pQh + go);
        cp16(sb + SC_TILE + so,     pQl + go);
        cp16(sb + 2 * SC_TILE + so, pKh + go);
        cp16(sb + 3 * SC_TILE + so, pKl + go);
    }
    CP_COMMIT(); CP_WAIT0();
    __syncthreads();

    const uint32_t aRow  = (uint32_t)(wm * 32 + (lane & 15));
    const uint32_t aByte = (uint32_t)((lane >> 4) * 16);
    const uint32_t bRow  = (uint32_t)(wn * 64 + (lane & 7) + ((lane >> 4) & 1) * 8);
    const uint32_t bByte = (uint32_t)(((lane >> 3) & 1) * 16);

    float acc[2][8][4] = {};

    #pragma unroll
    for (int kk = 0; kk < 4; kk++) {
        uint32_t ah[2][4], al[2][4];
        #pragma unroll
        for (int mi = 0; mi < 2; mi++) {
            const uint32_t ad = sb + (aRow + mi * 16) * RS2 + kk * 32 + aByte;
            LDSM4(ah[mi][0], ah[mi][1], ah[mi][2], ah[mi][3], ad);
            LDSM4(al[mi][0], al[mi][1], al[mi][2], al[mi][3], ad + SC_TILE);
        }
        #pragma unroll
        for (int hf = 0; hf < 2; hf++) {
            uint32_t bhr[4][2], blr[4][2];
            #pragma unroll
            for (int p = 0; p < 2; p++) {
                const uint32_t bd = sb + 2 * SC_TILE +
                    (bRow + (hf * 2 + p) * 16) * RS2 + kk * 32 + bByte;
                uint32_t t0, t1, t2, t3;
                LDSM4(t0, t1, t2, t3, bd);
                bhr[2 * p][0] = t0; bhr[2 * p][1] = t1;
                bhr[2 * p + 1][0] = t2; bhr[2 * p + 1][1] = t3;
                LDSM4(t0, t1, t2, t3, bd + SC_TILE);
                blr[2 * p][0] = t0; blr[2 * p][1] = t1;
                blr[2 * p + 1][0] = t2; blr[2 * p + 1][1] = t3;
            }
            #pragma unroll
            for (int mi = 0; mi < 2; mi++)
                #pragma unroll
                for (int nj = 0; nj < 4; nj++) {
                    float* d = acc[mi][hf * 4 + nj];
                    MMA_F16(d, ah[mi], bhr[nj]);
                    MMA_F16(d, ah[mi], blr[nj]);
                    MMA_F16(d, al[mi], bhr[nj]);
                }
        }
    }

    const float scale = *scale_p;
    const int trow = lane >> 2;
    const int tc   = (lane & 3) * 2;
    const size_t base = ((size_t)bh * Sc) * Sc;
    const int slot = blockIdx.x * 2 + wn;
    float* pm = g_pm + ((size_t)bh * 8 + slot) * Sc;
    float* ps = g_ps + ((size_t)bh * 8 + slot) * Sc;

    #pragma unroll
    for (int mi = 0; mi < 2; mi++) {
        const int r = q0 + wm * 32 + mi * 16 + trow;
        float mx0 = -3.402823466e38f, mx1 = -3.402823466e38f;
        // pass 1: compute, write scores, track per-thread max
        #pragma unroll
        for (int ni = 0; ni < 8; ni++) {
            const int col = n0 + wn * 64 + ni * 8 + tc;
            const size_t o0 = base + (size_t)r * Sc + col;
            const size_t o1 = base + (size_t)(r + 8) * Sc + col;
            const float2 p0 = *(const float2*)(prev + o0);
            const float2 p1 = *(const float2*)(prev + o1);
            float2 w0, w1;
            w0.x = fmaf(acc[mi][ni][0], scale, p0.x);
            w0.y = fmaf(acc[mi][ni][1], scale, p0.y);
            w1.x = fmaf(acc[mi][ni][2], scale, p1.x);
            w1.y = fmaf(acc[mi][ni][3], scale, p1.y);
            *(float2*)(scores + o0) = w0;
            *(float2*)(scores + o1) = w1;
            mx0 = fmaxf(mx0, fmaxf(w0.x, w0.y));
            mx1 = fmaxf(mx1, fmaxf(w1.x, w1.y));
        }
        // reduce max across the 4 tc lanes (lane&3)
        #pragma unroll
        for (int o = 1; o < 4; o <<= 1) {
            mx0 = fmaxf(mx0, __shfl_xor_sync(0xffffffffu, mx0, o));
            mx1 = fmaxf(mx1, __shfl_xor_sync(0xffffffffu, mx1, o));
        }
        // pass 2: recompute (deterministic) and accumulate exp-sums
        float s0 = 0.0f, s1 = 0.0f;
        #pragma unroll
        for (int ni = 0; ni < 8; ni++) {
            const int col = n0 + wn * 64 + ni * 8 + tc;
            const size_t o0 = base + (size_t)r * Sc + col;
            const size_t o1 = base + (size_t)(r + 8) * Sc + col;
            const float2 p0 = *(const float2*)(prev + o0);
            const float2 p1 = *(const float2*)(prev + o1);
            s0 += __expf(fmaf(acc[mi][ni][0], scale, p0.x) - mx0) +
                  __expf(fmaf(acc[mi][ni][1], scale, p0.y) - mx0);
            s1 += __expf(fmaf(acc[mi][ni][2], scale, p1.x) - mx1) +
                  __expf(fmaf(acc[mi][ni][3], scale, p1.y) - mx1);
        }
        #pragma unroll
        for (int o = 1; o < 4; o <<= 1) {
            s0 += __shfl_xor_sync(0xffffffffu, s0, o);
            s1 += __shfl_xor_sync(0xffffffffu, s1, o);
        }
        if ((lane & 3) == 0) {
            pm[r]     = mx0;  ps[r]     = s0;
            pm[r + 8] = mx1;  ps[r + 8] = s1;
        }
    }
}

// ===================== fused softmax*gate + ctx (stats precomputed) ========
// One block per (b,h,128 q-rows). Combine 8 per-row partials -> (m, 1/sum) in
// smem, then single streaming pass: 4 chunks of 128 keys (read scores once +
// gate, write attn fp32, stash fp16 hi/lo, 2-pass MMA with prefetched Vh).
#define RS3 272                        // 128 halfs = 256B + 16B pad
#define SG_AH (128 * RS3)              // 34816 per attn operand
#define SG_VT (128 * 144)              // 18432 V chunk
#define SG_SMEM (2 * SG_AH + SG_VT)    // 88064

__global__ void __launch_bounds__(256, 2)
sgc_tc(const float* __restrict__ scores, float* __restrict__ attn,
       __half* __restrict__ Ch, __half* __restrict__ Cl)
{
    extern __shared__ char dsm[];
    __shared__ float sm_m[128];
    __shared__ float sm_inv[128];
    const uint32_t sA = smem_u32(dsm);
    const uint32_t sV = sA + 2 * SG_AH;
    const int tid  = threadIdx.x;
    const int lane = tid & 31;
    const int wid  = tid >> 5;
    const int wm   = wid & 3;
    const int wn   = wid >> 2;
    const int bh = blockIdx.y;
    const int b  = bh >> 4;
    const int h  = bh & 15;
    const int q0 = blockIdx.x * 128;

    const float*  sbase = scores + ((size_t)bh * Sc + q0) * Sc;
    float*        abase = attn   + ((size_t)bh * Sc + q0) * Sc;
    const __half* gbase = g_gt + (size_t)(b * Sc + q0) * Gc + (size_t)h * Sc;
    const char*   pVh   = (const char*)g_vh + ((size_t)(b * Sc) * Dc + h * DKc) * 2;

    // combine per-row partial stats (threads 0..127, one row each)
    if (tid < 128) {
        const int row = q0 + tid;
        float mj[8];
        float m = -3.402823466e38f;
        #pragma unroll
        for (int j = 0; j < 8; j++) {
            mj[j] = g_pm[((size_t)bh * 8 + j) * Sc + row];
            m = fmaxf(m, mj[j]);
        }
        float s = 0.0f;
        #pragma unroll
        for (int j = 0; j < 8; j++)
            s += g_ps[((size_t)bh * 8 + j) * Sc + row] * __expf(mj[j] - m);
        sm_m[tid]   = m;
        sm_inv[tid] = 1.0f / s;
    }
    __syncthreads();

    const uint32_t aRow  = (uint32_t)(wm * 32 + (lane & 15));
    const uint32_t aByte = (uint32_t)((lane >> 4) * 16);
    const uint32_t vRowL = (uint32_t)(lane & 15);
    const uint32_t vColB = (uint32_t)((wn * 32 + (lane >> 4) * 8) * 2);

    float acc[2][4][4] = {};

    for (int c = 0; c < 4; c++) {
        // prefetch V chunk (128 rows x 128B hi)
        #pragma unroll
        for (int i = 0; i < 4; i++) {
            const int ci  = tid + i * 256;
            const int row = ci >> 3;
            const int seg = (ci & 7) * 16;
            cp16(sV + (uint32_t)(row * 144 + seg),
                 pVh + (size_t)(c * 128 + row) * (Dc * 2) + seg);
        }
        CP_COMMIT();

        // softmax * gate: read scores chunk once, write attn, stash fp16 hi/lo
        #pragma unroll
        for (int rr = 0; rr < 16; rr++) {
            const int r = wid * 16 + rr;
            const float mrow = sm_m[r];
            const float irow = sm_inv[r];
            const size_t off = (size_t)r * Sc + c * 128 + lane * 4;
            const float4 s4 = *(const float4*)(sbase + off);
            const __half2* g2 = (const __half2*)(gbase + (size_t)r * Gc + c * 128 + lane * 4);
            const __half2 ga = g2[0];
            const __half2 gb2 = g2[1];
            float4 a4;
            a4.x = __low2float(ga)   * (__expf(s4.x - mrow) * irow);
            a4.y = __high2float(ga)  * (__expf(s4.y - mrow) * irow);
            a4.z = __low2float(gb2)  * (__expf(s4.z - mrow) * irow);
            a4.w = __high2float(gb2) * (__expf(s4.w - mrow) * irow);
            *(float4*)(abase + off) = a4;

            const __half h0 = __float2half_rn(a4.x);
            const __half h1 = __float2half_rn(a4.y);
            const __half h2 = __float2half_rn(a4.z);
            const __half h3 = __float2half_rn(a4.w);
            const __half2 ph0 = __halves2half2(h0, h1);
            const __half2 ph1 = __halves2half2(h2, h3);
            const __half2 pl0 = __halves2half2(
                __float2half_rn(a4.x - __half2float(h0)),
                __float2half_rn(a4.y - __half2float(h1)));
            const __half2 pl1 = __halves2half2(
                __float2half_rn(a4.z - __half2float(h2)),
                __float2half_rn(a4.w - __half2float(h3)));
            const uint32_t so = (uint32_t)(r * RS3 + lane * 8);
            *(uint32_t*)(dsm + so)             = *(const uint32_t*)&ph0;
            *(uint32_t*)(dsm + so + 4)         = *(const uint32_t*)&ph1;
            *(uint32_t*)(dsm + SG_AH + so)     = *(const uint32_t*)&pl0;
            *(uint32_t*)(dsm + SG_AH + so + 4) = *(const uint32_t*)&pl1;
        }
        CP_WAIT0();
        __syncthreads();

        // ctx MMA over this chunk (K = 128 keys)
        #pragma unroll
        for (int kk = 0; kk < 8; kk++) {
            uint32_t ah[2][4], al[2][4];
            #pragma unroll
            for (int mi = 0; mi < 2; mi++) {
                const uint32_t ad = sA + (aRow + mi * 16) * RS3 + kk * 32 + aByte;
                LDSM4(ah[mi][0], ah[mi][1], ah[mi][2], ah[mi][3], ad);
                LDSM4(al[mi][0], al[mi][1], al[mi][2], al[mi][3], ad + SG_AH);
            }
            uint32_t bh_[4][2];
            #pragma unroll
            for (int p = 0; p < 2; p++) {
                const uint32_t vd = sV + (kk * 16 + vRowL) * 144 + vColB + p * 32;
                uint32_t t0, t1, t2, t3;
                LDSM4T(t0, t1, t2, t3, vd);
                bh_[2 * p][0] = t0; bh_[2 * p][1] = t1;
                bh_[2 * p + 1][0] = t2; bh_[2 * p + 1][1] = t3;
            }
            #pragma unroll
            for (int mi = 0; mi < 2; mi++)
                #pragma unroll
                for (int nj = 0; nj < 4; nj++) {
                    float* d = acc[mi][nj];
                    MMA_F16(d, ah[mi], bh_[nj]);
                    MMA_F16(d, al[mi], bh_[nj]);
                }
        }
        __syncthreads();
    }

    // epilogue: ctx fp16 hi/lo at [(b*S+q), h*64 + col]
    const int trow = lane >> 2;
    const int tc   = (lane & 3) * 2;
    #pragma unroll
    for (int mi = 0; mi < 2; mi++) {
        const int r = b * Sc + q0 + wm * 32 + mi * 16 + trow;
        #pragma unroll
        for (int nj = 0; nj < 4; nj++) {
            const int col = h * DKc + wn * 32 + nj * 8 + tc;
            const float v00 = acc[mi][nj][0], v01 = acc[mi][nj][1];
            const float v10 = acc[mi][nj][2], v11 = acc[mi][nj][3];
            const __half h00 = __float2half_rn(v00);
            const __half h01 = __float2half_rn(v01);
            const __half h10 = __float2half_rn(v10);
            const __half h11 = __float2half_rn(v11);
            *(__half2*)(Ch + (size_t)r * Dc + col) = __halves2half2(h00, h01);
            *(__half2*)(Cl + (size_t)r * Dc + col) = __halves2half2(
                __float2half_rn(v00 - __half2float(h00)),
                __float2half_rn(v01 - __half2float(h01)));
            *(__half2*)(Ch + (size_t)(r + 8) * Dc + col) = __halves2half2(h10, h11);
            *(__half2*)(Cl + (size_t)(r + 8) * Dc + col) = __halves2half2(
                __float2half_rn(v10 - __half2float(h10)),
                __float2half_rn(v11 - __half2float(h11)));
        }
    }
}

// ---------------------------------------------------------------------------
extern "C" void kernel_launch(void* const* d_in, const int* in_sizes, int n_in,
                              void* d_out, int out_size)
{
    (void)in_sizes; (void)n_in; (void)out_size;

    const float* Q     = (const float*)d_in[0];
    const float* prev  = (const float*)d_in[1];
    const float* Wq    = (const float*)d_in[2];
    const float* bq    = (const float*)d_in[3];
    const float* Wk    = (const float*)d_in[4];
    const float* bk    = (const float*)d_in[5];
    const float* Wv    = (const float*)d_in[6];
    const float* bv    = (const float*)d_in[7];
    const float* Wg    = (const float*)d_in[8];
    const float* bg    = (const float*)d_in[9];
    const float* Wo    = (const float*)d_in[10];
    const float* bo    = (const float*)d_in[11];
    const float* scale = (const float*)d_in[12];

    float* out    = (float*)d_out;
    float* attn   = out + OUT_ELEMS;
    float* scores = attn + ATTN_ELEMS;

    __half *gb, *ah, *al, *wh, *wl, *qh, *ql, *kh, *kl, *vh;
    cudaGetSymbolAddress((void**)&gb, g_gt);
    cudaGetSymbolAddress((void**)&ah, g_ah);
    cudaGetSymbolAddress((void**)&al, g_al);
    cudaGetSymbolAddress((void**)&wh, g_wh);
    cudaGetSymbolAddress((void**)&wl, g_wl);
    cudaGetSymbolAddress((void**)&qh, g_qh);
    cudaGetSymbolAddress((void**)&ql, g_ql);
    cudaGetSymbolAddress((void**)&kh, g_kh);
    cudaGetSymbolAddress((void**)&kl, g_kl);
    cudaGetSymbolAddress((void**)&vh, g_vh);

    cudaFuncSetAttribute((const void*)gemm_mma<0, 3>, cudaFuncAttributeMaxDynamicSharedMemorySize, GEMM_SMEM);
    cudaFuncSetAttribute((const void*)gemm_mma<1, 3>, cudaFuncAttributeMaxDynamicSharedMemorySize, GEMM_SMEM);
    cudaFuncSetAttribute((const void*)gemm_mma<0, 2>, cudaFuncAttributeMaxDynamicSharedMemorySize, GEMM_SMEM);
    cudaFuncSetAttribute((const void*)gemm_mma<2, 2>, cudaFuncAttributeMaxDynamicSharedMemorySize, GEMM_SMEM);
    cudaFuncSetAttribute((const void*)gemm_mma<2, 1>, cudaFuncAttributeMaxDynamicSharedMemorySize, GEMM_SMEM);
    cudaFuncSetAttribute((const void*)scores_tc,      cudaFuncAttributeMaxDynamicSharedMemorySize, SC_SMEM);
    cudaFuncSetAttribute((const void*)sgc_tc,         cudaFuncAttributeMaxDynamicSharedMemorySize, SG_SMEM);

    const dim3 tblk(32, 8);
    const long long nQ4 = (long long)Mc * Dc / 4;

    // split input activations into fp16 hi/lo
    split_kernel<<<(int)(nQ4 / 256), 256>>>(Q, ah, al, nQ4);

    // q/k projections -> fp16 hi/lo (3-pass, feed scores which is checked)
    transpose_split<<<dim3(Dc / 32, Dc / 32), tblk>>>(Wq, wh, wl, Dc, Dc);
    gemm_mma<1, 3><<<dim3(Dc / 128, Mc / 128), 256, GEMM_SMEM>>>(ah, al, wh, wl, bq, nullptr, qh, ql, Dc, Dc);
    transpose_split<<<dim3(Dc / 32, Dc / 32), tblk>>>(Wk, wh, wl, Dc, Dc);
    gemm_mma<1, 3><<<dim3(Dc / 128, Mc / 128), 256, GEMM_SMEM>>>(ah, al, wh, wl, bk, nullptr, kh, kl, Dc, Dc);
    // v projection -> fp16 hi only (2-pass: ctx consumes v at fp16 anyway)
    transpose_split<<<dim3(Dc / 32, Dc / 32), tblk>>>(Wv, wh, wl, Dc, Dc);
    gemm_mma<2, 2><<<dim3(Dc / 128, Mc / 128), 256, GEMM_SMEM>>>(ah, al, wh, wl, bv, nullptr, vh, nullptr, Dc, Dc);
    // gate projection (N = 8192) -> fp16, 1-pass (post-softmax path)
    transpose_split<<<dim3(Gc / 32, Dc / 32), tblk>>>(Wg, wh, wl, Dc, Gc);
    gemm_mma<2, 1><<<dim3(Gc / 128, Mc / 128), 256, GEMM_SMEM>>>(ah, al, wh, wl, bg, nullptr, gb, nullptr, Gc, Dc);

    // scores = q k^T * scale + prev (3-pass) + per-row softmax partial stats
    scores_tc<<<dim3(4, 4, Bc * Hc), 256, SC_SMEM>>>(prev, scale, scores);

    // fused: attn = gate * softmax(scores); ctx = attn @ v -> fp16 hi/lo ah/al
    sgc_tc<<<dim3(4, Bc * Hc), 256, SG_SMEM>>>(scores, attn, ah, al);

    // out = ctx @ Wo + bo (2-pass: weight-lo dropped)
    transpose_split<<<dim3(Dc / 32, Dc / 32), tblk>>>(Wo, wh, wl, Dc, Dc);
    gemm_mma<0, 2><<<dim3(Dc / 128, Mc / 128), 256, GEMM_SMEM>>>(ah, al, wh, wl, bo, out, nullptr, nullptr, Dc, Dc);
}

// round 13
// speedup vs baseline: 1.0342x; 1.0342x over previous
#include <cuda_runtime.h>
#include <cuda_fp16.h>
#include <cstdint>
#include <cstddef>

// Problem constants
#define Bc  16
#define Sc  512
#define Dc  1024
#define Hc  16
#define DKc 64
#define Mc  8192   // B*S
#define Gc  8192   // H*S

#define OUT_ELEMS  8388608LL
#define ATTN_ELEMS 67108864LL

// -------------------- device scratch (static globals; no allocs) -----------
__device__ __half g_gt [(size_t)Mc * Gc];     // gate [b*S+s][h*S+k] fp16
__device__ __half g_ah[(size_t)Mc * Dc];      // activation hi / later ctx hi
__device__ __half g_al[(size_t)Mc * Dc];      // activation lo / later ctx lo
__device__ __half g_wh[(size_t)Gc * Dc];      // weight^T hi [N,K]
__device__ __half g_wl[(size_t)Gc * Dc];      // weight^T lo
__device__ __half g_qh[(size_t)Mc * Dc];
__device__ __half g_ql[(size_t)Mc * Dc];
__device__ __half g_kh[(size_t)Mc * Dc];
__device__ __half g_kl[(size_t)Mc * Dc];
__device__ __half g_vh[(size_t)Mc * Dc];

// ===================== PTX helpers (sm_80-level only) ======================
__device__ __forceinline__ uint32_t smem_u32(const void* p) {
    uint32_t a;
    asm("{ .reg .u64 t; cvta.to.shared.u64 t, %1; cvt.u32.u64 %0, t; }" : "=r"(a) : "l"(p));
    return a;
}
__device__ __forceinline__ void cp16(uint32_t smem, const void* g) {
    asm volatile("cp.async.cg.shared.global [%0], [%1], 16;\n" :: "r"(smem), "l"(g));
}
#define CP_COMMIT() asm volatile("cp.async.commit_group;" ::: "memory")
#define CP_WAIT0()  asm volatile("cp.async.wait_group 0;" ::: "memory")

#define LDSM4(r0, r1, r2, r3, addr) \
    asm volatile("ldmatrix.sync.aligned.m8n8.x4.shared.b16 {%0,%1,%2,%3}, [%4];" \
        : "=r"(r0), "=r"(r1), "=r"(r2), "=r"(r3) : "r"(addr))
#define LDSM4T(r0, r1, r2, r3, addr) \
    asm volatile("ldmatrix.sync.aligned.m8n8.x4.trans.shared.b16 {%0,%1,%2,%3}, [%4];" \
        : "=r"(r0), "=r"(r1), "=r"(r2), "=r"(r3) : "r"(addr))

#define MMA_F16(d, a, b) \
    asm volatile("mma.sync.aligned.m16n8k16.row.col.f32.f16.f16.f32 " \
        "{%0,%1,%2,%3},{%4,%5,%6,%7},{%8,%9},{%0,%1,%2,%3};" \
        : "+f"((d)[0]), "+f"((d)[1]), "+f"((d)[2]), "+f"((d)[3]) \
        : "r"((a)[0]), "r"((a)[1]), "r"((a)[2]), "r"((a)[3]), \
          "r"((b)[0]), "r"((b)[1]))

// ===================== conversion kernels ==================================
__global__ void __launch_bounds__(256)
split_kernel(const float* __restrict__ x, __half* __restrict__ hi,
             __half* __restrict__ lo, long long n4)
{
    long long i = ((long long)blockIdx.x * 256 + threadIdx.x);
    if (i >= n4) return;
    const float4 v = ((const float4*)x)[i];
    const __half h0 = __float2half_rn(v.x);
    const __half h1 = __float2half_rn(v.y);
    const __half h2 = __float2half_rn(v.z);
    const __half h3 = __float2half_rn(v.w);
    ((__half2*)hi)[i * 2 + 0] = __halves2half2(h0, h1);
    ((__half2*)hi)[i * 2 + 1] = __halves2half2(h2, h3);
    ((__half2*)lo)[i * 2 + 0] = __halves2half2(
        __float2half_rn(v.x - __half2float(h0)),
        __float2half_rn(v.y - __half2float(h1)));
    ((__half2*)lo)[i * 2 + 1] = __halves2half2(
        __float2half_rn(v.z - __half2float(h2)),
        __float2half_rn(v.w - __half2float(h3)));
}

// W[K][N] fp32 -> T[N][K] fp16 hi/lo
__global__ void __launch_bounds__(256)
transpose_split(const float* __restrict__ W, __half* __restrict__ Th,
                __half* __restrict__ Tl, int K, int N)
{
    __shared__ float t[32][33];
    const int n0 = blockIdx.x * 32, k0 = blockIdx.y * 32;
    const int tx = threadIdx.x, ty = threadIdx.y;  // (32, 8)
    #pragma unroll
    for (int p = 0; p < 4; p++) {
        const int kk = ty + p * 8;
        t[kk][tx] = W[(size_t)(k0 + kk) * N + n0 + tx];
    }
    __syncthreads();
    #pragma unroll
    for (int p = 0; p < 4; p++) {
        const int nn = ty + p * 8;
        const float v = t[tx][nn];
        const __half h = __float2half_rn(v);
        Th[(size_t)(n0 + nn) * K + k0 + tx] = h;
        Tl[(size_t)(n0 + nn) * K + k0 + tx] = __float2half_rn(v - __half2float(h));
    }
}

// ===================== mma.sync split-fp16 GEMM (multi-stage) ==============
// PASSES==3: Ah@Bh + Ah@Bl + Al@Bh (4 tiles/stage, 2 stages).
// PASSES==2: Ah@Bh + Al@Bh          (3 tiles/stage, 3 stages).
// PASSES==1: Ah@Bh                  (2 tiles/stage, 4 stages).
// MODE 0: C fp32 (+bias). MODE 1: fp16 hi/lo split. MODE 2: fp16 hi only.
#define RS 80
#define TILE_B   (128 * RS)

template<int MODE, int PASSES>
__global__ void __launch_bounds__(256, 2)
gemm_mma(const __half* __restrict__ Ah, const __half* __restrict__ Al,
         const __half* __restrict__ Bh, const __half* __restrict__ Bl,
         const float* __restrict__ bias, float* __restrict__ C,
         __half* __restrict__ Ch, __half* __restrict__ Cl,
         int Ntot, int K)
{
    constexpr int TILES  = (PASSES == 3) ? 4 : (PASSES == 2) ? 3 : 2;
    constexpr int STAGES = (PASSES == 3) ? 2 : (PASSES == 2) ? 3 : 4;
    constexpr uint32_t STB    = (uint32_t)TILES * TILE_B;
    constexpr uint32_t OFF_AL = TILE_B;                            // PASSES>=2
    constexpr uint32_t OFF_BH = (PASSES >= 2 ? 2u : 1u) * TILE_B;
    constexpr uint32_t OFF_BL = 3u * TILE_B;                       // PASSES==3

    extern __shared__ char dsm[];
    const uint32_t sb0 = smem_u32(dsm);
    const int tid  = threadIdx.x;
    const int lane = tid & 31;
    const int wid  = tid >> 5;
    const int wm   = wid & 3;
    const int wn   = wid >> 2;
    const int m0   = blockIdx.y * 128;
    const int n0   = blockIdx.x * 128;

    const size_t Kb = (size_t)K * 2;
    const int NK = K >> 5;

    const char* pAh = (const char*)Ah + (size_t)m0 * Kb;
    const char* pAl = (const char*)Al + (size_t)m0 * Kb;
    const char* pBh = (const char*)Bh + (size_t)n0 * Kb;
    const char* pBl = (const char*)Bl + (size_t)n0 * Kb;

    auto load_stage = [&](int kt, int s) {
        const uint32_t sb = sb0 + (uint32_t)s * STB;
        const size_t kb = (size_t)kt * 64;
        #pragma unroll
        for (int i = 0; i < 2; i++) {
            const int c   = tid + i * 256;
            const int row = c >> 2;
            const int seg = (c & 3) * 16;
            const uint32_t so = (uint32_t)(row * RS + seg);
            const size_t go = (size_t)row * Kb + kb + seg;
            cp16(sb + so, pAh + go);
            if (PASSES >= 2) cp16(sb + OFF_AL + so, pAl + go);
            cp16(sb + OFF_BH + so, pBh + go);
            if (PASSES == 3) cp16(sb + OFF_BL + so, pBl + go);
        }
    };

    const uint32_t aRow  = (uint32_t)(wm * 32 + (lane & 15));
    const uint32_t aByte = (uint32_t)((lane >> 4) * 16);
    const uint32_t bRow  = (uint32_t)(wn * 64 + (lane & 7) + ((lane >> 4) & 1) * 8);
    const uint32_t bByte = (uint32_t)(((lane >> 3) & 1) * 16);

    float acc[2][8][4] = {};

    // prologue: fill STAGES-1 stages, one commit group each
    #pragma unroll
    for (int s = 0; s < STAGES - 1; s++) { load_stage(s, s); CP_COMMIT(); }

    for (int kt = 0; kt < NK; kt++) {
        // stage kt is ready when at most STAGES-2 groups remain outstanding
        asm volatile("cp.async.wait_group %0;" :: "n"(STAGES - 2) : "memory");
        __syncthreads();

        // always commit exactly one group per iteration (empty at the tail)
        if (kt + STAGES - 1 < NK) load_stage(kt + STAGES - 1, (kt + STAGES - 1) % STAGES);
        CP_COMMIT();

        const uint32_t sb = sb0 + (uint32_t)(kt % STAGES) * STB;

        #pragma unroll
        for (int kk = 0; kk < 2; kk++) {
            uint32_t ah[2][4], al[2][4];
            #pragma unroll
            for (int mi = 0; mi < 2; mi++) {
                const uint32_t ad = sb + (aRow + mi * 16) * RS + kk * 32 + aByte;
                LDSM4(ah[mi][0], ah[mi][1], ah[mi][2], ah[mi][3], ad);
                if (PASSES >= 2)
                    LDSM4(al[mi][0], al[mi][1], al[mi][2], al[mi][3], ad + OFF_AL);
            }
            #pragma unroll
            for (int hf = 0; hf < 2; hf++) {
                uint32_t bh[4][2], bl[4][2];
                #pragma unroll
                for (int p = 0; p < 2; p++) {
                    const uint32_t bd = sb + OFF_BH +
                        (bRow + (hf * 2 + p) * 16) * RS + kk * 32 + bByte;
                    uint32_t t0, t1, t2, t3;
                    LDSM4(t0, t1, t2, t3, bd);
                    bh[2 * p][0] = t0; bh[2 * p][1] = t1;
                    bh[2 * p + 1][0] = t2; bh[2 * p + 1][1] = t3;
                    if (PASSES == 3) {
                        LDSM4(t0, t1, t2, t3, bd + (OFF_BL - OFF_BH));
                        bl[2 * p][0] = t0; bl[2 * p][1] = t1;
                        bl[2 * p + 1][0] = t2; bl[2 * p + 1][1] = t3;
                    }
                }
                #pragma unroll
                for (int mi = 0; mi < 2; mi++)
                    #pragma unroll
                    for (int nj = 0; nj < 4; nj++) {
                        float* d = acc[mi][hf * 4 + nj];
                        MMA_F16(d, ah[mi], bh[nj]);
                        if (PASSES == 3) MMA_F16(d, ah[mi], bl[nj]);
                        if (PASSES >= 2) MMA_F16(d, al[mi], bh[nj]);
                    }
            }
        }
    }

    const int trow = lane >> 2;
    const int tc   = (lane & 3) * 2;
    #pragma unroll
    for (int mi = 0; mi < 2; mi++) {
        const int r = m0 + wm * 32 + mi * 16 + trow;
        #pragma unroll
        for (int ni = 0; ni < 8; ni++) {
            const int col = n0 + wn * 64 + ni * 8 + tc;
            const float2 bv = *(const float2*)(bias + col);
            const float v00 = acc[mi][ni][0] + bv.x;
            const float v01 = acc[mi][ni][1] + bv.y;
            const float v10 = acc[mi][ni][2] + bv.x;
            const float v11 = acc[mi][ni][3] + bv.y;
            if (MODE == 0) {
                float2 o0 = {v00, v01}, o1 = {v10, v11};
                *(float2*)(C + (size_t)r * Ntot + col) = o0;
                *(float2*)(C + (size_t)(r + 8) * Ntot + col) = o1;
            } else if (MODE == 1) {
                const __half h00 = __float2half_rn(v00);
                const __half h01 = __float2half_rn(v01);
                const __half h10 = __float2half_rn(v10);
                const __half h11 = __float2half_rn(v11);
                *(__half2*)(Ch + (size_t)r * Ntot + col) = __halves2half2(h00, h01);
                *(__half2*)(Cl + (size_t)r * Ntot + col) = __halves2half2(
                    __float2half_rn(v00 - __half2float(h00)),
                    __float2half_rn(v01 - __half2float(h01)));
                *(__half2*)(Ch + (size_t)(r + 8) * Ntot + col) = __halves2half2(h10, h11);
                *(__half2*)(Cl + (size_t)(r + 8) * Ntot + col) = __halves2half2(
                    __float2half_rn(v10 - __half2float(h10)),
                    __float2half_rn(v11 - __half2float(h11)));
            } else {  // MODE 2: fp16 hi only
                *(__half2*)(Ch + (size_t)r * Ntot + col) =
                    __halves2half2(__float2half_rn(v00), __float2half_rn(v01));
                *(__half2*)(Ch + (size_t)(r + 8) * Ntot + col) =
                    __halves2half2(__float2half_rn(v10), __float2half_rn(v11));
            }
        }
    }
}

// smem sizes per instantiation
#define SMEM_P3 (2 * 4 * TILE_B)   // 81920
#define SMEM_P2 (3 * 3 * TILE_B)   // 92160
#define SMEM_P1 (4 * 2 * TILE_B)   // 81920

// ===================== scores via mma: q k^T * scale + prev ================
#define RS2 144
#define SC_TILE (128 * RS2)
#define SC_SMEM (4 * SC_TILE)         // 73728: Qh | Ql | Kh | Kl

__global__ void __launch_bounds__(256, 2)
scores_tc(const float* __restrict__ prev, const float* __restrict__ scale_p,
          float* __restrict__ scores)
{
    extern __shared__ char dsm[];
    const uint32_t sb = smem_u32(dsm);
    const int tid  = threadIdx.x;
    const int lane = tid & 31;
    const int wid  = tid >> 5;
    const int wm   = wid & 3;
    const int wn   = wid >> 2;
    const int bh = blockIdx.z;
    const int b  = bh >> 4;
    const int h  = bh & 15;
    const int q0 = blockIdx.y * 128;
    const int n0 = blockIdx.x * 128;

    const char* pQh = (const char*)g_qh + ((size_t)(b * Sc + q0) * Dc + h * DKc) * 2;
    const char* pQl = (const char*)g_ql + ((size_t)(b * Sc + q0) * Dc + h * DKc) * 2;
    const char* pKh = (const char*)g_kh + ((size_t)(b * Sc + n0) * Dc + h * DKc) * 2;
    const char* pKl = (const char*)g_kl + ((size_t)(b * Sc + n0) * Dc + h * DKc) * 2;
    #pragma unroll
    for (int i = 0; i < 4; i++) {
        const int c   = tid + i * 256;
        const int row = c >> 3;
        const int seg = (c & 7) * 16;
        const uint32_t so = (uint32_t)(row * RS2 + seg);
        const size_t go = (size_t)row * (Dc * 2) + seg;
        cp16(sb + so,               pQh + go);
        cp16(sb + SC_TILE + so,     pQl + go);
        cp16(sb + 2 * SC_TILE + so, pKh + go);
        cp16(sb + 3 * SC_TILE + so, pKl + go);
    }
    CP_COMMIT(); CP_WAIT0();
    __syncthreads();

    const uint32_t aRow  = (uint32_t)(wm * 32 + (lane & 15));
    const uint32_t aByte = (uint32_t)((lane >> 4) * 16);
    const uint32_t bRow  = (uint32_t)(wn * 64 + (lane & 7) + ((lane >> 4) & 1) * 8);
    const uint32_t bByte = (uint32_t)(((lane >> 3) & 1) * 16);

    float acc[2][8][4] = {};

    #pragma unroll
    for (int kk = 0; kk < 4; kk++) {
        uint32_t ah[2][4], al[2][4];
        #pragma unroll
        for (int mi = 0; mi < 2; mi++) {
            const uint32_t ad = sb + (aRow + mi * 16) * RS2 + kk * 32 + aByte;
            LDSM4(ah[mi][0], ah[mi][1], ah[mi][2], ah[mi][3], ad);
            LDSM4(al[mi][0], al[mi][1], al[mi][2], al[mi][3], ad + SC_TILE);
        }
        #pragma unroll
        for (int hf = 0; hf < 2; hf++) {
            uint32_t bhr[4][2], blr[4][2];
            #pragma unroll
            for (int p = 0; p < 2; p++) {
                const uint32_t bd = sb + 2 * SC_TILE +
                    (bRow + (hf * 2 + p) * 16) * RS2 + kk * 32 + bByte;
                uint32_t t0, t1, t2, t3;
                LDSM4(t0, t1, t2, t3, bd);
                bhr[2 * p][0] = t0; bhr[2 * p][1] = t1;
                bhr[2 * p + 1][0] = t2; bhr[2 * p + 1][1] = t3;
                LDSM4(t0, t1, t2, t3, bd + SC_TILE);
                blr[2 * p][0] = t0; blr[2 * p][1] = t1;
                blr[2 * p + 1][0] = t2; blr[2 * p + 1][1] = t3;
            }
            #pragma unroll
            for (int mi = 0; mi < 2; mi++)
                #pragma unroll
                for (int nj = 0; nj < 4; nj++) {
                    float* d = acc[mi][hf * 4 + nj];
                    MMA_F16(d, ah[mi], bhr[nj]);
                    MMA_F16(d, ah[mi], blr[nj]);
                    MMA_F16(d, al[mi], bhr[nj]);
                }
        }
    }

    const float scale = *scale_p;
    const int trow = lane >> 2;
    const int tc   = (lane & 3) * 2;
    const size_t base = ((size_t)(b * Hc + h) * Sc) * Sc;
    #pragma unroll
    for (int mi = 0; mi < 2; mi++) {
        const int r = q0 + wm * 32 + mi * 16 + trow;
        #pragma unroll
        for (int ni = 0; ni < 8; ni++) {
            const int col = n0 + wn * 64 + ni * 8 + tc;
            const size_t o0 = base + (size_t)r * Sc + col;
            const size_t o1 = base + (size_t)(r + 8) * Sc + col;
            const float2 p0 = *(const float2*)(prev + o0);
            const float2 p1 = *(const float2*)(prev + o1);
            float2 w0, w1;
            w0.x = fmaf(acc[mi][ni][0], scale, p0.x);
            w0.y = fmaf(acc[mi][ni][1], scale, p0.y);
            w1.x = fmaf(acc[mi][ni][2], scale, p1.x);
            w1.y = fmaf(acc[mi][ni][3], scale, p1.y);
            *(float2*)(scores + o0) = w0;
            *(float2*)(scores + o1) = w1;
        }
    }
}

// ===================== softmax * gate (fp16 gate) ==========================
__global__ void __launch_bounds__(256)
softmax_gate_kernel(float* __restrict__ attn, const float* __restrict__ scores)
{
    const int warp = threadIdx.x >> 5;
    const int lane = threadIdx.x & 31;
    const long long row = (long long)blockIdx.x * 8 + warp;

    const float* srow = scores + row * Sc;
    float*       arow = attn   + row * Sc;

    const int b  = (int)(row >> 13);
    const int hq = (int)(row & 8191);
    const int h  = hq >> 9;
    const int q  = hq & 511;
    const __half* grow = g_gt + (size_t)(b * Sc + q) * Gc + (size_t)h * Sc;

    float4 x[4];
    float mx = -3.402823466e38f;
    #pragma unroll
    for (int t = 0; t < 4; t++) {
        x[t] = *(const float4*)(srow + t * 128 + lane * 4);
        mx = fmaxf(mx, fmaxf(fmaxf(x[t].x, x[t].y), fmaxf(x[t].z, x[t].w)));
    }
    #pragma unroll
    for (int o = 16; o > 0; o >>= 1)
        mx = fmaxf(mx, __shfl_xor_sync(0xffffffffu, mx, o));

    float sum = 0.0f;
    #pragma unroll
    for (int t = 0; t < 4; t++) {
        x[t].x = __expf(x[t].x - mx);
        x[t].y = __expf(x[t].y - mx);
        x[t].z = __expf(x[t].z - mx);
        x[t].w = __expf(x[t].w - mx);
        sum += (x[t].x + x[t].y) + (x[t].z + x[t].w);
    }
    #pragma unroll
    for (int o = 16; o > 0; o >>= 1)
        sum += __shfl_xor_sync(0xffffffffu, sum, o);
    const float inv = 1.0f / sum;

    #pragma unroll
    for (int t = 0; t < 4; t++) {
        const __half2* g2 = (const __half2*)(grow + t * 128 + lane * 4);
        const __half2 ga = g2[0];
        const __half2 gb2 = g2[1];
        float4 o;
        o.x = __low2float(ga)  * x[t].x * inv;
        o.y = __high2float(ga) * x[t].y * inv;
        o.z = __low2float(gb2)  * x[t].z * inv;
        o.w = __high2float(gb2) * x[t].w * inv;
        *(float4*)(arow + t * 128 + lane * 4) = o;
    }
}

// ===================== ctx = attn @ v via mma (2-pass) =====================
#define CT_A    (128 * RS2)
#define CT_V    (64 * RS2)
#define CT_SMEM (2 * CT_A + CT_V)   // Ah | Al | Vh

__global__ void __launch_bounds__(256, 2)
ctx_tc(const float* __restrict__ attn,
       __half* __restrict__ Ch, __half* __restrict__ Cl)
{
    extern __shared__ char dsm[];
    const uint32_t sA = smem_u32(dsm);
    const uint32_t sV = sA + 2 * CT_A;
    const int tid  = threadIdx.x;
    const int lane = tid & 31;
    const int wid  = tid >> 5;
    const int wm   = wid & 3;
    const int wn   = wid >> 2;
    const int bh = blockIdx.y;
    const int b  = bh >> 4;
    const int h  = bh & 15;
    const int q0 = blockIdx.x * 128;

    const size_t abase = ((size_t)(b * Hc + h) * Sc + q0) * Sc;
    const char* pVh = (const char*)g_vh + ((size_t)(b * Sc) * Dc + h * DKc) * 2;

    const uint32_t aRow  = (uint32_t)(wm * 32 + (lane & 15));
    const uint32_t aByte = (uint32_t)((lane >> 4) * 16);
    const uint32_t vRowL = (uint32_t)(lane & 15);
    const uint32_t vColB = (uint32_t)((wn * 32 + (lane >> 4) * 8) * 2);

    float acc[2][4][4] = {};

    for (int kt = 0; kt < 8; kt++) {
        __syncthreads();
        #pragma unroll
        for (int i = 0; i < 2; i++) {
            const int c   = tid + i * 256;
            const int row = c >> 3;
            const int seg = (c & 7) * 16;
            const uint32_t so = (uint32_t)(row * RS2 + seg);
            const size_t go = (size_t)(kt * 64 + row) * (Dc * 2) + seg;
            cp16(sV + so, pVh + go);
        }
        CP_COMMIT();
        #pragma unroll
        for (int i = 0; i < 8; i++) {
            const int c   = tid + i * 256;
            const int row = c >> 4;
            const int f4  = c & 15;
            const float4 v = *(const float4*)(attn + abase + (size_t)row * Sc + kt * 64 + f4 * 4);
            const __half h0 = __float2half_rn(v.x);
            const __half h1 = __float2half_rn(v.y);
            const __half h2 = __float2half_rn(v.z);
            const __half h3 = __float2half_rn(v.w);
            const __half2 ph0 = __halves2half2(h0, h1);
            const __half2 ph1 = __halves2half2(h2, h3);
            const __half2 pl0 = __halves2half2(
                __float2half_rn(v.x - __half2float(h0)),
                __float2half_rn(v.y - __half2float(h1)));
            const __half2 pl1 = __halves2half2(
                __float2half_rn(v.z - __half2float(h2)),
                __float2half_rn(v.w - __half2float(h3)));
            const uint32_t so = (uint32_t)(row * RS2 + f4 * 8);
            *(uint32_t*)(dsm + (so))            = *(const uint32_t*)&ph0;
            *(uint32_t*)(dsm + (so + 4))        = *(const uint32_t*)&ph1;
            *(uint32_t*)(dsm + (CT_A + so))     = *(const uint32_t*)&pl0;
            *(uint32_t*)(dsm + (CT_A + so + 4)) = *(const uint32_t*)&pl1;
        }
        CP_WAIT0();
        __syncthreads();

        #pragma unroll
        for (int kk = 0; kk < 4; kk++) {
            uint32_t ah[2][4], al[2][4];
            #pragma unroll
            for (int mi = 0; mi < 2; mi++) {
                const uint32_t ad = sA + (aRow + mi * 16) * RS2 + kk * 32 + aByte;
                LDSM4(ah[mi][0], ah[mi][1], ah[mi][2], ah[mi][3], ad);
                LDSM4(al[mi][0], al[mi][1], al[mi][2], al[mi][3], ad + CT_A);
            }
            uint32_t bh_[4][2];
            #pragma unroll
            for (int p = 0; p < 2; p++) {
                const uint32_t vd = sV + (kk * 16 + vRowL) * RS2 + vColB + p * 32;
                uint32_t t0, t1, t2, t3;
                LDSM4T(t0, t1, t2, t3, vd);
                bh_[2 * p][0] = t0; bh_[2 * p][1] = t1;
                bh_[2 * p + 1][0] = t2; bh_[2 * p + 1][1] = t3;
            }
            #pragma unroll
            for (int mi = 0; mi < 2; mi++)
                #pragma unroll
                for (int nj = 0; nj < 4; nj++) {
                    float* d = acc[mi][nj];
                    MMA_F16(d, ah[mi], bh_[nj]);
                    MMA_F16(d, al[mi], bh_[nj]);
                }
        }
    }

    const int trow = lane >> 2;
    const int tc   = (lane & 3) * 2;
    #pragma unroll
    for (int mi = 0; mi < 2; mi++) {
        const int r = b * Sc + q0 + wm * 32 + mi * 16 + trow;
        #pragma unroll
        for (int nj = 0; nj < 4; nj++) {
            const int col = h * DKc + wn * 32 + nj * 8 + tc;
            const float v00 = acc[mi][nj][0], v01 = acc[mi][nj][1];
            const float v10 = acc[mi][nj][2], v11 = acc[mi][nj][3];
            const __half h00 = __float2half_rn(v00);
            const __half h01 = __float2half_rn(v01);
            const __half h10 = __float2half_rn(v10);
            const __half h11 = __float2half_rn(v11);
            *(__half2*)(Ch + (size_t)r * Dc + col) = __halves2half2(h00, h01);
            *(__half2*)(Cl + (size_t)r * Dc + col) = __halves2half2(
                __float2half_rn(v00 - __half2float(h00)),
                __float2half_rn(v01 - __half2float(h01)));
            *(__half2*)(Ch + (size_t)(r + 8) * Dc + col) = __halves2half2(h10, h11);
            *(__half2*)(Cl + (size_t)(r + 8) * Dc + col) = __halves2half2(
                __float2half_rn(v10 - __half2float(h10)),
                __float2half_rn(v11 - __half2float(h11)));
        }
    }
}

// ---------------------------------------------------------------------------
extern "C" void kernel_launch(void* const* d_in, const int* in_sizes, int n_in,
                              void* d_out, int out_size)
{
    (void)in_sizes; (void)n_in; (void)out_size;

    const float* Q     = (const float*)d_in[0];
    const float* prev  = (const float*)d_in[1];
    const float* Wq    = (const float*)d_in[2];
    const float* bq    = (const float*)d_in[3];
    const float* Wk    = (const float*)d_in[4];
    const float* bk    = (const float*)d_in[5];
    const float* Wv    = (const float*)d_in[6];
    const float* bv    = (const float*)d_in[7];
    const float* Wg    = (const float*)d_in[8];
    const float* bg    = (const float*)d_in[9];
    const float* Wo    = (const float*)d_in[10];
    const float* bo    = (const float*)d_in[11];
    const float* scale = (const float*)d_in[12];

    float* out    = (float*)d_out;
    float* attn   = out + OUT_ELEMS;
    float* scores = attn + ATTN_ELEMS;

    __half *gb, *ah, *al, *wh, *wl, *qh, *ql, *kh, *kl, *vh;
    cudaGetSymbolAddress((void**)&gb, g_gt);
    cudaGetSymbolAddress((void**)&ah, g_ah);
    cudaGetSymbolAddress((void**)&al, g_al);
    cudaGetSymbolAddress((void**)&wh, g_wh);
    cudaGetSymbolAddress((void**)&wl, g_wl);
    cudaGetSymbolAddress((void**)&qh, g_qh);
    cudaGetSymbolAddress((void**)&ql, g_ql);
    cudaGetSymbolAddress((void**)&kh, g_kh);
    cudaGetSymbolAddress((void**)&kl, g_kl);
    cudaGetSymbolAddress((void**)&vh, g_vh);

    cudaFuncSetAttribute((const void*)gemm_mma<1, 3>, cudaFuncAttributeMaxDynamicSharedMemorySize, SMEM_P3);
    cudaFuncSetAttribute((const void*)gemm_mma<0, 2>, cudaFuncAttributeMaxDynamicSharedMemorySize, SMEM_P2);
    cudaFuncSetAttribute((const void*)gemm_mma<2, 2>, cudaFuncAttributeMaxDynamicSharedMemorySize, SMEM_P2);
    cudaFuncSetAttribute((const void*)gemm_mma<2, 1>, cudaFuncAttributeMaxDynamicSharedMemorySize, SMEM_P1);
    cudaFuncSetAttribute((const void*)scores_tc,      cudaFuncAttributeMaxDynamicSharedMemorySize, SC_SMEM);
    cudaFuncSetAttribute((const void*)ctx_tc,         cudaFuncAttributeMaxDynamicSharedMemorySize, CT_SMEM);

    const dim3 tblk(32, 8);
    const long long nQ4 = (long long)Mc * Dc / 4;

    // split input activations into fp16 hi/lo
    split_kernel<<<(int)(nQ4 / 256), 256>>>(Q, ah, al, nQ4);

    // q/k projections -> fp16 hi/lo (3-pass, feed scores which is checked)
    transpose_split<<<dim3(Dc / 32, Dc / 32), tblk>>>(Wq, wh, wl, Dc, Dc);
    gemm_mma<1, 3><<<dim3(Dc / 128, Mc / 128), 256, SMEM_P3>>>(ah, al, wh, wl, bq, nullptr, qh, ql, Dc, Dc);
    transpose_split<<<dim3(Dc / 32, Dc / 32), tblk>>>(Wk, wh, wl, Dc, Dc);
    gemm_mma<1, 3><<<dim3(Dc / 128, Mc / 128), 256, SMEM_P3>>>(ah, al, wh, wl, bk, nullptr, kh, kl, Dc, Dc);
    // v projection -> fp16 hi only (2-pass: ctx consumes v at fp16 anyway)
    transpose_split<<<dim3(Dc / 32, Dc / 32), tblk>>>(Wv, wh, wl, Dc, Dc);
    gemm_mma<2, 2><<<dim3(Dc / 128, Mc / 128), 256, SMEM_P2>>>(ah, al, wh, wl, bv, nullptr, vh, nullptr, Dc, Dc);
    // gate projection (N = 8192) -> fp16, 1-pass (post-softmax path)
    transpose_split<<<dim3(Gc / 32, Dc / 32), tblk>>>(Wg, wh, wl, Dc, Gc);
    gemm_mma<2, 1><<<dim3(Gc / 128, Mc / 128), 256, SMEM_P1>>>(ah, al, wh, wl, bg, nullptr, gb, nullptr, Gc, Dc);

    // scores = q k^T * scale + prev (3-pass, pristine)
    scores_tc<<<dim3(4, 4, Bc * Hc), 256, SC_SMEM>>>(prev, scale, scores);
    // attn = gate * softmax(scores)
    softmax_gate_kernel<<<(Bc * Hc * Sc) / 8, 256>>>(attn, scores);
    // ctx = attn @ v (2-pass) -> fp16 hi/lo into ah/al
    ctx_tc<<<dim3(4, Bc * Hc), 256, CT_SMEM>>>(attn, ah, al);

    // out = ctx @ Wo + bo (2-pass: weight-lo dropped)
    transpose_split<<<dim3(Dc / 32, Dc / 32), tblk>>>(Wo, wh, wl, Dc, Dc);
    gemm_mma<0, 2><<<dim3(Dc / 128, Mc / 128), 256, SMEM_P2>>>(ah, al, wh, wl, bo, out, nullptr, nullptr, Dc, Dc);
}

// round 14
// speedup vs baseline: 1.1267x; 1.0894x over previous
#include <cuda_runtime.h>
#include <cuda_fp16.h>
#include <cstdint>
#include <cstddef>

// Problem constants
#define Bc  16
#define Sc  512
#define Dc  1024
#define Hc  16
#define DKc 64
#define Mc  8192   // B*S
#define Gc  8192   // H*S

#define OUT_ELEMS  8388608LL
#define ATTN_ELEMS 67108864LL

// -------------------- device scratch (static globals; no allocs) -----------
__device__ __half g_gt [(size_t)Mc * Gc];     // gate [b*S+s][h*S+k] fp16
__device__ __half g_ah[(size_t)Mc * Dc];      // activation hi / later ctx hi
__device__ __half g_al[(size_t)Mc * Dc];      // activation lo / later ctx lo
__device__ __half g_wh[(size_t)Gc * Dc];      // weight^T hi [N,K]
__device__ __half g_wl[(size_t)Gc * Dc];      // weight^T lo
__device__ __half g_qh[(size_t)Mc * Dc];
__device__ __half g_ql[(size_t)Mc * Dc];
__device__ __half g_kh[(size_t)Mc * Dc];
__device__ __half g_vh[(size_t)Mc * Dc];

// ===================== PTX helpers (sm_80-level only) ======================
__device__ __forceinline__ uint32_t smem_u32(const void* p) {
    uint32_t a;
    asm("{ .reg .u64 t; cvta.to.shared.u64 t, %1; cvt.u32.u64 %0, t; }" : "=r"(a) : "l"(p));
    return a;
}
__device__ __forceinline__ void cp16(uint32_t smem, const void* g) {
    asm volatile("cp.async.cg.shared.global [%0], [%1], 16;\n" :: "r"(smem), "l"(g));
}
#define CP_COMMIT() asm volatile("cp.async.commit_group;" ::: "memory")
#define CP_WAIT0()  asm volatile("cp.async.wait_group 0;" ::: "memory")

#define LDSM4(r0, r1, r2, r3, addr) \
    asm volatile("ldmatrix.sync.aligned.m8n8.x4.shared.b16 {%0,%1,%2,%3}, [%4];" \
        : "=r"(r0), "=r"(r1), "=r"(r2), "=r"(r3) : "r"(addr))
#define LDSM4T(r0, r1, r2, r3, addr) \
    asm volatile("ldmatrix.sync.aligned.m8n8.x4.trans.shared.b16 {%0,%1,%2,%3}, [%4];" \
        : "=r"(r0), "=r"(r1), "=r"(r2), "=r"(r3) : "r"(addr))

#define MMA_F16(d, a, b) \
    asm volatile("mma.sync.aligned.m16n8k16.row.col.f32.f16.f16.f32 " \
        "{%0,%1,%2,%3},{%4,%5,%6,%7},{%8,%9},{%0,%1,%2,%3};" \
        : "+f"((d)[0]), "+f"((d)[1]), "+f"((d)[2]), "+f"((d)[3]) \
        : "r"((a)[0]), "r"((a)[1]), "r"((a)[2]), "r"((a)[3]), \
          "r"((b)[0]), "r"((b)[1]))

// ===================== conversion kernels ==================================
__global__ void __launch_bounds__(256)
split_kernel(const float* __restrict__ x, __half* __restrict__ hi,
             __half* __restrict__ lo, long long n4)
{
    long long i = ((long long)blockIdx.x * 256 + threadIdx.x);
    if (i >= n4) return;
    const float4 v = ((const float4*)x)[i];
    const __half h0 = __float2half_rn(v.x);
    const __half h1 = __float2half_rn(v.y);
    const __half h2 = __float2half_rn(v.z);
    const __half h3 = __float2half_rn(v.w);
    ((__half2*)hi)[i * 2 + 0] = __halves2half2(h0, h1);
    ((__half2*)hi)[i * 2 + 1] = __halves2half2(h2, h3);
    ((__half2*)lo)[i * 2 + 0] = __halves2half2(
        __float2half_rn(v.x - __half2float(h0)),
        __float2half_rn(v.y - __half2float(h1)));
    ((__half2*)lo)[i * 2 + 1] = __halves2half2(
        __float2half_rn(v.z - __half2float(h2)),
        __float2half_rn(v.w - __half2float(h3)));
}

// W[K][N] fp32 -> T[N][K] fp16 hi/lo
__global__ void __launch_bounds__(256)
transpose_split(const float* __restrict__ W, __half* __restrict__ Th,
                __half* __restrict__ Tl, int K, int N)
{
    __shared__ float t[32][33];
    const int n0 = blockIdx.x * 32, k0 = blockIdx.y * 32;
    const int tx = threadIdx.x, ty = threadIdx.y;  // (32, 8)
    #pragma unroll
    for (int p = 0; p < 4; p++) {
        const int kk = ty + p * 8;
        t[kk][tx] = W[(size_t)(k0 + kk) * N + n0 + tx];
    }
    __syncthreads();
    #pragma unroll
    for (int p = 0; p < 4; p++) {
        const int nn = ty + p * 8;
        const float v = t[tx][nn];
        const __half h = __float2half_rn(v);
        Th[(size_t)(n0 + nn) * K + k0 + tx] = h;
        Tl[(size_t)(n0 + nn) * K + k0 + tx] = __float2half_rn(v - __half2float(h));
    }
}

// ===================== mma.sync split-fp16 GEMM (multi-stage) ==============
// PASSES==3: Ah@Bh + Ah@Bl + Al@Bh (4 tiles/stage, 2 stages).
// PASSES==2: Ah@Bh + Al@Bh          (3 tiles/stage, 3 stages).
// PASSES==1: Ah@Bh                  (2 tiles/stage, 4 stages).
// MODE 0: C fp32 (+bias). MODE 1: fp16 hi/lo split. MODE 2: fp16 hi only.
#define RS 80
#define TILE_B   (128 * RS)

template<int MODE, int PASSES>
__global__ void __launch_bounds__(256, 2)
gemm_mma(const __half* __restrict__ Ah, const __half* __restrict__ Al,
         const __half* __restrict__ Bh, const __half* __restrict__ Bl,
         const float* __restrict__ bias, float* __restrict__ C,
         __half* __restrict__ Ch, __half* __restrict__ Cl,
         int Ntot, int K)
{
    constexpr int TILES  = (PASSES == 3) ? 4 : (PASSES == 2) ? 3 : 2;
    constexpr int STAGES = (PASSES == 3) ? 2 : (PASSES == 2) ? 3 : 4;
    constexpr uint32_t STB    = (uint32_t)TILES * TILE_B;
    constexpr uint32_t OFF_AL = TILE_B;                            // PASSES>=2
    constexpr uint32_t OFF_BH = (PASSES >= 2 ? 2u : 1u) * TILE_B;
    constexpr uint32_t OFF_BL = 3u * TILE_B;                       // PASSES==3

    extern __shared__ char dsm[];
    const uint32_t sb0 = smem_u32(dsm);
    const int tid  = threadIdx.x;
    const int lane = tid & 31;
    const int wid  = tid >> 5;
    const int wm   = wid & 3;
    const int wn   = wid >> 2;
    const int m0   = blockIdx.y * 128;
    const int n0   = blockIdx.x * 128;

    const size_t Kb = (size_t)K * 2;
    const int NK = K >> 5;

    const char* pAh = (const char*)Ah + (size_t)m0 * Kb;
    const char* pAl = (const char*)Al + (size_t)m0 * Kb;
    const char* pBh = (const char*)Bh + (size_t)n0 * Kb;
    const char* pBl = (const char*)Bl + (size_t)n0 * Kb;

    auto load_stage = [&](int kt, int s) {
        const uint32_t sb = sb0 + (uint32_t)s * STB;
        const size_t kb = (size_t)kt * 64;
        #pragma unroll
        for (int i = 0; i < 2; i++) {
            const int c   = tid + i * 256;
            const int row = c >> 2;
            const int seg = (c & 3) * 16;
            const uint32_t so = (uint32_t)(row * RS + seg);
            const size_t go = (size_t)row * Kb + kb + seg;
            cp16(sb + so, pAh + go);
            if (PASSES >= 2) cp16(sb + OFF_AL + so, pAl + go);
            cp16(sb + OFF_BH + so, pBh + go);
            if (PASSES == 3) cp16(sb + OFF_BL + so, pBl + go);
        }
    };

    const uint32_t aRow  = (uint32_t)(wm * 32 + (lane & 15));
    const uint32_t aByte = (uint32_t)((lane >> 4) * 16);
    const uint32_t bRow  = (uint32_t)(wn * 64 + (lane & 7) + ((lane >> 4) & 1) * 8);
    const uint32_t bByte = (uint32_t)(((lane >> 3) & 1) * 16);

    float acc[2][8][4] = {};

    #pragma unroll
    for (int s = 0; s < STAGES - 1; s++) { load_stage(s, s); CP_COMMIT(); }

    for (int kt = 0; kt < NK; kt++) {
        asm volatile("cp.async.wait_group %0;" :: "n"(STAGES - 2) : "memory");
        __syncthreads();

        if (kt + STAGES - 1 < NK) load_stage(kt + STAGES - 1, (kt + STAGES - 1) % STAGES);
        CP_COMMIT();

        const uint32_t sb = sb0 + (uint32_t)(kt % STAGES) * STB;

        #pragma unroll
        for (int kk = 0; kk < 2; kk++) {
            uint32_t ah[2][4], al[2][4];
            #pragma unroll
            for (int mi = 0; mi < 2; mi++) {
                const uint32_t ad = sb + (aRow + mi * 16) * RS + kk * 32 + aByte;
                LDSM4(ah[mi][0], ah[mi][1], ah[mi][2], ah[mi][3], ad);
                if (PASSES >= 2)
                    LDSM4(al[mi][0], al[mi][1], al[mi][2], al[mi][3], ad + OFF_AL);
            }
            #pragma unroll
            for (int hf = 0; hf < 2; hf++) {
                uint32_t bh[4][2], bl[4][2];
                #pragma unroll
                for (int p = 0; p < 2; p++) {
                    const uint32_t bd = sb + OFF_BH +
                        (bRow + (hf * 2 + p) * 16) * RS + kk * 32 + bByte;
                    uint32_t t0, t1, t2, t3;
                    LDSM4(t0, t1, t2, t3, bd);
                    bh[2 * p][0] = t0; bh[2 * p][1] = t1;
                    bh[2 * p + 1][0] = t2; bh[2 * p + 1][1] = t3;
                    if (PASSES == 3) {
                        LDSM4(t0, t1, t2, t3, bd + (OFF_BL - OFF_BH));
                        bl[2 * p][0] = t0; bl[2 * p][1] = t1;
                        bl[2 * p + 1][0] = t2; bl[2 * p + 1][1] = t3;
                    }
                }
                #pragma unroll
                for (int mi = 0; mi < 2; mi++)
                    #pragma unroll
                    for (int nj = 0; nj < 4; nj++) {
                        float* d = acc[mi][hf * 4 + nj];
                        MMA_F16(d, ah[mi], bh[nj]);
                        if (PASSES == 3) MMA_F16(d, ah[mi], bl[nj]);
                        if (PASSES >= 2) MMA_F16(d, al[mi], bh[nj]);
                    }
            }
        }
    }

    const int trow = lane >> 2;
    const int tc   = (lane & 3) * 2;
    #pragma unroll
    for (int mi = 0; mi < 2; mi++) {
        const int r = m0 + wm * 32 + mi * 16 + trow;
        #pragma unroll
        for (int ni = 0; ni < 8; ni++) {
            const int col = n0 + wn * 64 + ni * 8 + tc;
            const float2 bv = *(const float2*)(bias + col);
            const float v00 = acc[mi][ni][0] + bv.x;
            const float v01 = acc[mi][ni][1] + bv.y;
            const float v10 = acc[mi][ni][2] + bv.x;
            const float v11 = acc[mi][ni][3] + bv.y;
            if (MODE == 0) {
                float2 o0 = {v00, v01}, o1 = {v10, v11};
                *(float2*)(C + (size_t)r * Ntot + col) = o0;
                *(float2*)(C + (size_t)(r + 8) * Ntot + col) = o1;
            } else if (MODE == 1) {
                const __half h00 = __float2half_rn(v00);
                const __half h01 = __float2half_rn(v01);
                const __half h10 = __float2half_rn(v10);
                const __half h11 = __float2half_rn(v11);
                *(__half2*)(Ch + (size_t)r * Ntot + col) = __halves2half2(h00, h01);
                *(__half2*)(Cl + (size_t)r * Ntot + col) = __halves2half2(
                    __float2half_rn(v00 - __half2float(h00)),
                    __float2half_rn(v01 - __half2float(h01)));
                *(__half2*)(Ch + (size_t)(r + 8) * Ntot + col) = __halves2half2(h10, h11);
                *(__half2*)(Cl + (size_t)(r + 8) * Ntot + col) = __halves2half2(
                    __float2half_rn(v10 - __half2float(h10)),
                    __float2half_rn(v11 - __half2float(h11)));
            } else {  // MODE 2: fp16 hi only
                *(__half2*)(Ch + (size_t)r * Ntot + col) =
                    __halves2half2(__float2half_rn(v00), __float2half_rn(v01));
                *(__half2*)(Ch + (size_t)(r + 8) * Ntot + col) =
                    __halves2half2(__float2half_rn(v10), __float2half_rn(v11));
            }
        }
    }
}

// smem sizes per instantiation
#define SMEM_P3 (2 * 4 * TILE_B)   // 81920
#define SMEM_P2 (3 * 3 * TILE_B)   // 92160
#define SMEM_P1 (4 * 2 * TILE_B)   // 81920

// ===================== scores via mma (2-pass): (qh+ql) @ kh^T =============
// grid (4, 4, 256): 128x128 tile per (b,h). K = 64. Tiles: Qh | Ql | Kh.
#define RS2 144
#define SC_TILE (128 * RS2)
#define SC_SMEM (3 * SC_TILE)         // 55296

__global__ void __launch_bounds__(256, 2)
scores_tc(const float* __restrict__ prev, const float* __restrict__ scale_p,
          float* __restrict__ scores)
{
    extern __shared__ char dsm[];
    const uint32_t sb = smem_u32(dsm);
    const int tid  = threadIdx.x;
    const int lane = tid & 31;
    const int wid  = tid >> 5;
    const int wm   = wid & 3;
    const int wn   = wid >> 2;
    const int bh = blockIdx.z;
    const int b  = bh >> 4;
    const int h  = bh & 15;
    const int q0 = blockIdx.y * 128;
    const int n0 = blockIdx.x * 128;

    const char* pQh = (const char*)g_qh + ((size_t)(b * Sc + q0) * Dc + h * DKc) * 2;
    const char* pQl = (const char*)g_ql + ((size_t)(b * Sc + q0) * Dc + h * DKc) * 2;
    const char* pKh = (const char*)g_kh + ((size_t)(b * Sc + n0) * Dc + h * DKc) * 2;
    #pragma unroll
    for (int i = 0; i < 4; i++) {
        const int c   = tid + i * 256;
        const int row = c >> 3;
        const int seg = (c & 7) * 16;
        const uint32_t so = (uint32_t)(row * RS2 + seg);
        const size_t go = (size_t)row * (Dc * 2) + seg;
        cp16(sb + so,               pQh + go);
        cp16(sb + SC_TILE + so,     pQl + go);
        cp16(sb + 2 * SC_TILE + so, pKh + go);
    }
    CP_COMMIT(); CP_WAIT0();
    __syncthreads();

    const uint32_t aRow  = (uint32_t)(wm * 32 + (lane & 15));
    const uint32_t aByte = (uint32_t)((lane >> 4) * 16);
    const uint32_t bRow  = (uint32_t)(wn * 64 + (lane & 7) + ((lane >> 4) & 1) * 8);
    const uint32_t bByte = (uint32_t)(((lane >> 3) & 1) * 16);

    float acc[2][8][4] = {};

    #pragma unroll
    for (int kk = 0; kk < 4; kk++) {
        uint32_t ah[2][4], al[2][4];
        #pragma unroll
        for (int mi = 0; mi < 2; mi++) {
            const uint32_t ad = sb + (aRow + mi * 16) * RS2 + kk * 32 + aByte;
            LDSM4(ah[mi][0], ah[mi][1], ah[mi][2], ah[mi][3], ad);
            LDSM4(al[mi][0], al[mi][1], al[mi][2], al[mi][3], ad + SC_TILE);
        }
        #pragma unroll
        for (int hf = 0; hf < 2; hf++) {
            uint32_t bhr[4][2];
            #pragma unroll
            for (int p = 0; p < 2; p++) {
                const uint32_t bd = sb + 2 * SC_TILE +
                    (bRow + (hf * 2 + p) * 16) * RS2 + kk * 32 + bByte;
                uint32_t t0, t1, t2, t3;
                LDSM4(t0, t1, t2, t3, bd);
                bhr[2 * p][0] = t0; bhr[2 * p][1] = t1;
                bhr[2 * p + 1][0] = t2; bhr[2 * p + 1][1] = t3;
            }
            #pragma unroll
            for (int mi = 0; mi < 2; mi++)
                #pragma unroll
                for (int nj = 0; nj < 4; nj++) {
                    float* d = acc[mi][hf * 4 + nj];
                    MMA_F16(d, ah[mi], bhr[nj]);
                    MMA_F16(d, al[mi], bhr[nj]);
                }
        }
    }

    const float scale = *scale_p;
    const int trow = lane >> 2;
    const int tc   = (lane & 3) * 2;
    const size_t base = ((size_t)(b * Hc + h) * Sc) * Sc;
    #pragma unroll
    for (int mi = 0; mi < 2; mi++) {
        const int r = q0 + wm * 32 + mi * 16 + trow;
        #pragma unroll
        for (int ni = 0; ni < 8; ni++) {
            const int col = n0 + wn * 64 + ni * 8 + tc;
            const size_t o0 = base + (size_t)r * Sc + col;
            const size_t o1 = base + (size_t)(r + 8) * Sc + col;
            const float2 p0 = *(const float2*)(prev + o0);
            const float2 p1 = *(const float2*)(prev + o1);
            float2 w0, w1;
            w0.x = fmaf(acc[mi][ni][0], scale, p0.x);
            w0.y = fmaf(acc[mi][ni][1], scale, p0.y);
            w1.x = fmaf(acc[mi][ni][2], scale, p1.x);
            w1.y = fmaf(acc[mi][ni][3], scale, p1.y);
            *(float2*)(scores + o0) = w0;
            *(float2*)(scores + o1) = w1;
        }
    }
}

// ===================== softmax * gate (fp16 gate) ==========================
__global__ void __launch_bounds__(256)
softmax_gate_kernel(float* __restrict__ attn, const float* __restrict__ scores)
{
    const int warp = threadIdx.x >> 5;
    const int lane = threadIdx.x & 31;
    const long long row = (long long)blockIdx.x * 8 + warp;

    const float* srow = scores + row * Sc;
    float*       arow = attn   + row * Sc;

    const int b  = (int)(row >> 13);
    const int hq = (int)(row & 8191);
    const int h  = hq >> 9;
    const int q  = hq & 511;
    const __half* grow = g_gt + (size_t)(b * Sc + q) * Gc + (size_t)h * Sc;

    float4 x[4];
    float mx = -3.402823466e38f;
    #pragma unroll
    for (int t = 0; t < 4; t++) {
        x[t] = *(const float4*)(srow + t * 128 + lane * 4);
        mx = fmaxf(mx, fmaxf(fmaxf(x[t].x, x[t].y), fmaxf(x[t].z, x[t].w)));
    }
    #pragma unroll
    for (int o = 16; o > 0; o >>= 1)
        mx = fmaxf(mx, __shfl_xor_sync(0xffffffffu, mx, o));

    float sum = 0.0f;
    #pragma unroll
    for (int t = 0; t < 4; t++) {
        x[t].x = __expf(x[t].x - mx);
        x[t].y = __expf(x[t].y - mx);
        x[t].z = __expf(x[t].z - mx);
        x[t].w = __expf(x[t].w - mx);
        sum += (x[t].x + x[t].y) + (x[t].z + x[t].w);
    }
    #pragma unroll
    for (int o = 16; o > 0; o >>= 1)
        sum += __shfl_xor_sync(0xffffffffu, sum, o);
    const float inv = 1.0f / sum;

    #pragma unroll
    for (int t = 0; t < 4; t++) {
        const __half2* g2 = (const __half2*)(grow + t * 128 + lane * 4);
        const __half2 ga = g2[0];
        const __half2 gb2 = g2[1];
        float4 o;
        o.x = __low2float(ga)  * x[t].x * inv;
        o.y = __high2float(ga) * x[t].y * inv;
        o.z = __low2float(gb2)  * x[t].z * inv;
        o.w = __high2float(gb2) * x[t].w * inv;
        *(float4*)(arow + t * 128 + lane * 4) = o;
    }
}

// ===================== ctx = attn @ v via mma (2-pass) =====================
#define CT_A    (128 * RS2)
#define CT_V    (64 * RS2)
#define CT_SMEM (2 * CT_A + CT_V)   // Ah | Al | Vh

__global__ void __launch_bounds__(256, 2)
ctx_tc(const float* __restrict__ attn,
       __half* __restrict__ Ch, __half* __restrict__ Cl)
{
    extern __shared__ char dsm[];
    const uint32_t sA = smem_u32(dsm);
    const uint32_t sV = sA + 2 * CT_A;
    const int tid  = threadIdx.x;
    const int lane = tid & 31;
    const int wid  = tid >> 5;
    const int wm   = wid & 3;
    const int wn   = wid >> 2;
    const int bh = blockIdx.y;
    const int b  = bh >> 4;
    const int h  = bh & 15;
    const int q0 = blockIdx.x * 128;

    const size_t abase = ((size_t)(b * Hc + h) * Sc + q0) * Sc;
    const char* pVh = (const char*)g_vh + ((size_t)(b * Sc) * Dc + h * DKc) * 2;

    const uint32_t aRow  = (uint32_t)(wm * 32 + (lane & 15));
    const uint32_t aByte = (uint32_t)((lane >> 4) * 16);
    const uint32_t vRowL = (uint32_t)(lane & 15);
    const uint32_t vColB = (uint32_t)((wn * 32 + (lane >> 4) * 8) * 2);

    float acc[2][4][4] = {};

    for (int kt = 0; kt < 8; kt++) {
        __syncthreads();
        #pragma unroll
        for (int i = 0; i < 2; i++) {
            const int c   = tid + i * 256;
            const int row = c >> 3;
            const int seg = (c & 7) * 16;
            const uint32_t so = (uint32_t)(row * RS2 + seg);
            const size_t go = (size_t)(kt * 64 + row) * (Dc * 2) + seg;
            cp16(sV + so, pVh + go);
        }
        CP_COMMIT();
        #pragma unroll
        for (int i = 0; i < 8; i++) {
            const int c   = tid + i * 256;
            const int row = c >> 4;
            const int f4  = c & 15;
            const float4 v = *(const float4*)(attn + abase + (size_t)row * Sc + kt * 64 + f4 * 4);
            const __half h0 = __float2half_rn(v.x);
            const __half h1 = __float2half_rn(v.y);
            const __half h2 = __float2half_rn(v.z);
            const __half h3 = __float2half_rn(v.w);
            const __half2 ph0 = __halves2half2(h0, h1);
            const __half2 ph1 = __halves2half2(h2, h3);
            const __half2 pl0 = __halves2half2(
                __float2half_rn(v.x - __half2float(h0)),
                __float2half_rn(v.y - __half2float(h1)));
            const __half2 pl1 = __halves2half2(
                __float2half_rn(v.z - __half2float(h2)),
                __float2half_rn(v.w - __half2float(h3)));
            const uint32_t so = (uint32_t)(row * RS2 + f4 * 8);
            *(uint32_t*)(dsm + (so))            = *(const uint32_t*)&ph0;
            *(uint32_t*)(dsm + (so + 4))        = *(const uint32_t*)&ph1;
            *(uint32_t*)(dsm + (CT_A + so))     = *(const uint32_t*)&pl0;
            *(uint32_t*)(dsm + (CT_A + so + 4)) = *(const uint32_t*)&pl1;
        }
        CP_WAIT0();
        __syncthreads();

        #pragma unroll
        for (int kk = 0; kk < 4; kk++) {
            uint32_t ah[2][4], al[2][4];
            #pragma unroll
            for (int mi = 0; mi < 2; mi++) {
                const uint32_t ad = sA + (aRow + mi * 16) * RS2 + kk * 32 + aByte;
                LDSM4(ah[mi][0], ah[mi][1], ah[mi][2], ah[mi][3], ad);
                LDSM4(al[mi][0], al[mi][1], al[mi][2], al[mi][3], ad + CT_A);
            }
            uint32_t bh_[4][2];
            #pragma unroll
            for (int p = 0; p < 2; p++) {
                const uint32_t vd = sV + (kk * 16 + vRowL) * RS2 + vColB + p * 32;
                uint32_t t0, t1, t2, t3;
                LDSM4T(t0, t1, t2, t3, vd);
                bh_[2 * p][0] = t0; bh_[2 * p][1] = t1;
                bh_[2 * p + 1][0] = t2; bh_[2 * p + 1][1] = t3;
            }
            #pragma unroll
            for (int mi = 0; mi < 2; mi++)
                #pragma unroll
                for (int nj = 0; nj < 4; nj++) {
                    float* d = acc[mi][nj];
                    MMA_F16(d, ah[mi], bh_[nj]);
                    MMA_F16(d, al[mi], bh_[nj]);
                }
        }
    }

    const int trow = lane >> 2;
    const int tc   = (lane & 3) * 2;
    #pragma unroll
    for (int mi = 0; mi < 2; mi++) {
        const int r = b * Sc + q0 + wm * 32 + mi * 16 + trow;
        #pragma unroll
        for (int nj = 0; nj < 4; nj++) {
            const int col = h * DKc + wn * 32 + nj * 8 + tc;
            const float v00 = acc[mi][nj][0], v01 = acc[mi][nj][1];
            const float v10 = acc[mi][nj][2], v11 = acc[mi][nj][3];
            const __half h00 = __float2half_rn(v00);
            const __half h01 = __float2half_rn(v01);
            const __half h10 = __float2half_rn(v10);
            const __half h11 = __float2half_rn(v11);
            *(__half2*)(Ch + (size_t)r * Dc + col) = __halves2half2(h00, h01);
            *(__half2*)(Cl + (size_t)r * Dc + col) = __halves2half2(
                __float2half_rn(v00 - __half2float(h00)),
                __float2half_rn(v01 - __half2float(h01)));
            *(__half2*)(Ch + (size_t)(r + 8) * Dc + col) = __halves2half2(h10, h11);
            *(__half2*)(Cl + (size_t)(r + 8) * Dc + col) = __halves2half2(
                __float2half_rn(v10 - __half2float(h10)),
                __float2half_rn(v11 - __half2float(h11)));
        }
    }
}

// ---------------------------------------------------------------------------
extern "C" void kernel_launch(void* const* d_in, const int* in_sizes, int n_in,
                              void* d_out, int out_size)
{
    (void)in_sizes; (void)n_in; (void)out_size;

    const float* Q     = (const float*)d_in[0];
    const float* prev  = (const float*)d_in[1];
    const float* Wq    = (const float*)d_in[2];
    const float* bq    = (const float*)d_in[3];
    const float* Wk    = (const float*)d_in[4];
    const float* bk    = (const float*)d_in[5];
    const float* Wv    = (const float*)d_in[6];
    const float* bv    = (const float*)d_in[7];
    const float* Wg    = (const float*)d_in[8];
    const float* bg    = (const float*)d_in[9];
    const float* Wo    = (const float*)d_in[10];
    const float* bo    = (const float*)d_in[11];
    const float* scale = (const float*)d_in[12];

    float* out    = (float*)d_out;
    float* attn   = out + OUT_ELEMS;
    float* scores = attn + ATTN_ELEMS;

    __half *gb, *ah, *al, *wh, *wl, *qh, *ql, *kh, *vh;
    cudaGetSymbolAddress((void**)&gb, g_gt);
    cudaGetSymbolAddress((void**)&ah, g_ah);
    cudaGetSymbolAddress((void**)&al, g_al);
    cudaGetSymbolAddress((void**)&wh, g_wh);
    cudaGetSymbolAddress((void**)&wl, g_wl);
    cudaGetSymbolAddress((void**)&qh, g_qh);
    cudaGetSymbolAddress((void**)&ql, g_ql);
    cudaGetSymbolAddress((void**)&kh, g_kh);
    cudaGetSymbolAddress((void**)&vh, g_vh);

    cudaFuncSetAttribute((const void*)gemm_mma<1, 2>, cudaFuncAttributeMaxDynamicSharedMemorySize, SMEM_P2);
    cudaFuncSetAttribute((const void*)gemm_mma<0, 2>, cudaFuncAttributeMaxDynamicSharedMemorySize, SMEM_P2);
    cudaFuncSetAttribute((const void*)gemm_mma<2, 2>, cudaFuncAttributeMaxDynamicSharedMemorySize, SMEM_P2);
    cudaFuncSetAttribute((const void*)gemm_mma<2, 1>, cudaFuncAttributeMaxDynamicSharedMemorySize, SMEM_P1);
    cudaFuncSetAttribute((const void*)scores_tc,      cudaFuncAttributeMaxDynamicSharedMemorySize, SC_SMEM);
    cudaFuncSetAttribute((const void*)ctx_tc,         cudaFuncAttributeMaxDynamicSharedMemorySize, CT_SMEM);

    const dim3 tblk(32, 8);
    const long long nQ4 = (long long)Mc * Dc / 4;

    // split input activations into fp16 hi/lo
    split_kernel<<<(int)(nQ4 / 256), 256>>>(Q, ah, al, nQ4);

    // q projection -> fp16 hi/lo (2-pass: weight-lo dropped)
    transpose_split<<<dim3(Dc / 32, Dc / 32), tblk>>>(Wq, wh, wl, Dc, Dc);
    gemm_mma<1, 2><<<dim3(Dc / 128, Mc / 128), 256, SMEM_P2>>>(ah, al, wh, wl, bq, nullptr, qh, ql, Dc, Dc);
    // k projection -> fp16 hi only (2-pass; scores consumes k at fp16)
    transpose_split<<<dim3(Dc / 32, Dc / 32), tblk>>>(Wk, wh, wl, Dc, Dc);
    gemm_mma<2, 2><<<dim3(Dc / 128, Mc / 128), 256, SMEM_P2>>>(ah, al, wh, wl, bk, nullptr, kh, nullptr, Dc, Dc);
    // v projection -> fp16 hi only (2-pass)
    transpose_split<<<dim3(Dc / 32, Dc / 32), tblk>>>(Wv, wh, wl, Dc, Dc);
    gemm_mma<2, 2><<<dim3(Dc / 128, Mc / 128), 256, SMEM_P2>>>(ah, al, wh, wl, bv, nullptr, vh, nullptr, Dc, Dc);
    // gate projection (N = 8192) -> fp16, 1-pass (post-softmax path)
    transpose_split<<<dim3(Gc / 32, Dc / 32), tblk>>>(Wg, wh, wl, Dc, Gc);
    gemm_mma<2, 1><<<dim3(Gc / 128, Mc / 128), 256, SMEM_P1>>>(ah, al, wh, wl, bg, nullptr, gb, nullptr, Gc, Dc);

    // scores = (qh+ql) kh^T * scale + prev (2-pass)
    scores_tc<<<dim3(4, 4, Bc * Hc), 256, SC_SMEM>>>(prev, scale, scores);
    // attn = gate * softmax(scores)
    softmax_gate_kernel<<<(Bc * Hc * Sc) / 8, 256>>>(attn, scores);
    // ctx = attn @ v (2-pass) -> fp16 hi/lo into ah/al
    ctx_tc<<<dim3(4, Bc * Hc), 256, CT_SMEM>>>(attn, ah, al);

    // out = ctx @ Wo + bo (2-pass: weight-lo dropped)
    transpose_split<<<dim3(Dc / 32, Dc / 32), tblk>>>(Wo, wh, wl, Dc, Dc);
    gemm_mma<0, 2><<<dim3(Dc / 128, Mc / 128), 256, SMEM_P2>>>(ah, al, wh, wl, bo, out, nullptr, nullptr, Dc, Dc);
}

// round 15
// speedup vs baseline: 1.1916x; 1.0576x over previous
#include <cuda_runtime.h>
#include <cuda_fp16.h>
#include <cstdint>
#include <cstddef>

// Problem constants
#define Bc  16
#define Sc  512
#define Dc  1024
#define Hc  16
#define DKc 64
#define Mc  8192   // B*S
#define Gc  8192   // H*S

#define OUT_ELEMS  8388608LL
#define ATTN_ELEMS 67108864LL

// -------------------- device scratch (static globals; no allocs) -----------
__device__ __half g_gt [(size_t)Mc * Gc];     // gate [b*S+s][h*S+k] fp16
__device__ __half g_ah[(size_t)Mc * Dc];      // activation hi / later ctx hi
__device__ __half g_al[(size_t)Mc * Dc];      // activation lo
__device__ __half g_wh[(size_t)Gc * Dc];      // weight^T hi [N,K]
__device__ __half g_qh[(size_t)Mc * Dc];
__device__ __half g_ql[(size_t)Mc * Dc];
__device__ __half g_kh[(size_t)Mc * Dc];
__device__ __half g_vh[(size_t)Mc * Dc];

// ===================== PTX helpers (sm_80-level only) ======================
__device__ __forceinline__ uint32_t smem_u32(const void* p) {
    uint32_t a;
    asm("{ .reg .u64 t; cvta.to.shared.u64 t, %1; cvt.u32.u64 %0, t; }" : "=r"(a) : "l"(p));
    return a;
}
__device__ __forceinline__ void cp16(uint32_t smem, const void* g) {
    asm volatile("cp.async.cg.shared.global [%0], [%1], 16;\n" :: "r"(smem), "l"(g));
}
#define CP_COMMIT() asm volatile("cp.async.commit_group;" ::: "memory")
#define CP_WAIT0()  asm volatile("cp.async.wait_group 0;" ::: "memory")

#define LDSM4(r0, r1, r2, r3, addr) \
    asm volatile("ldmatrix.sync.aligned.m8n8.x4.shared.b16 {%0,%1,%2,%3}, [%4];" \
        : "=r"(r0), "=r"(r1), "=r"(r2), "=r"(r3) : "r"(addr))
#define LDSM4T(r0, r1, r2, r3, addr) \
    asm volatile("ldmatrix.sync.aligned.m8n8.x4.trans.shared.b16 {%0,%1,%2,%3}, [%4];" \
        : "=r"(r0), "=r"(r1), "=r"(r2), "=r"(r3) : "r"(addr))

#define MMA_F16(d, a, b) \
    asm volatile("mma.sync.aligned.m16n8k16.row.col.f32.f16.f16.f32 " \
        "{%0,%1,%2,%3},{%4,%5,%6,%7},{%8,%9},{%0,%1,%2,%3};" \
        : "+f"((d)[0]), "+f"((d)[1]), "+f"((d)[2]), "+f"((d)[3]) \
        : "r"((a)[0]), "r"((a)[1]), "r"((a)[2]), "r"((a)[3]), \
          "r"((b)[0]), "r"((b)[1]))

// ===================== conversion kernels ==================================
__global__ void __launch_bounds__(256)
split_kernel(const float* __restrict__ x, __half* __restrict__ hi,
             __half* __restrict__ lo, long long n4)
{
    long long i = ((long long)blockIdx.x * 256 + threadIdx.x);
    if (i >= n4) return;
    const float4 v = ((const float4*)x)[i];
    const __half h0 = __float2half_rn(v.x);
    const __half h1 = __float2half_rn(v.y);
    const __half h2 = __float2half_rn(v.z);
    const __half h3 = __float2half_rn(v.w);
    ((__half2*)hi)[i * 2 + 0] = __halves2half2(h0, h1);
    ((__half2*)hi)[i * 2 + 1] = __halves2half2(h2, h3);
    ((__half2*)lo)[i * 2 + 0] = __halves2half2(
        __float2half_rn(v.x - __half2float(h0)),
        __float2half_rn(v.y - __half2float(h1)));
    ((__half2*)lo)[i * 2 + 1] = __halves2half2(
        __float2half_rn(v.z - __half2float(h2)),
        __float2half_rn(v.w - __half2float(h3)));
}

// W[K][N] fp32 -> T[N][K] fp16 hi only (lo passes are never used downstream)
__global__ void __launch_bounds__(256)
transpose_hi(const float* __restrict__ W, __half* __restrict__ Th, int K, int N)
{
    __shared__ float t[32][33];
    const int n0 = blockIdx.x * 32, k0 = blockIdx.y * 32;
    const int tx = threadIdx.x, ty = threadIdx.y;  // (32, 8)
    #pragma unroll
    for (int p = 0; p < 4; p++) {
        const int kk = ty + p * 8;
        t[kk][tx] = W[(size_t)(k0 + kk) * N + n0 + tx];
    }
    __syncthreads();
    #pragma unroll
    for (int p = 0; p < 4; p++) {
        const int nn = ty + p * 8;
        Th[(size_t)(n0 + nn) * K + k0 + tx] = __float2half_rn(t[tx][nn]);
    }
}

// ===================== mma.sync split-fp16 GEMM (multi-stage) ==============
// PASSES==2: Ah@Bh + Al@Bh (3 tiles/stage, 3 stages).
// PASSES==1: Ah@Bh         (2 tiles/stage, 4 stages).
// MODE 0: C fp32 (+bias). MODE 1: fp16 hi/lo split. MODE 2: fp16 hi only.
#define RS 80
#define TILE_B   (128 * RS)

template<int MODE, int PASSES>
__global__ void __launch_bounds__(256, 2)
gemm_mma(const __half* __restrict__ Ah, const __half* __restrict__ Al,
         const __half* __restrict__ Bh,
         const float* __restrict__ bias, float* __restrict__ C,
         __half* __restrict__ Ch, __half* __restrict__ Cl,
         int Ntot, int K)
{
    constexpr int TILES  = (PASSES == 2) ? 3 : 2;
    constexpr int STAGES = (PASSES == 2) ? 3 : 4;
    constexpr uint32_t STB    = (uint32_t)TILES * TILE_B;
    constexpr uint32_t OFF_AL = TILE_B;                            // PASSES==2
    constexpr uint32_t OFF_BH = (PASSES >= 2 ? 2u : 1u) * TILE_B;

    extern __shared__ char dsm[];
    const uint32_t sb0 = smem_u32(dsm);
    const int tid  = threadIdx.x;
    const int lane = tid & 31;
    const int wid  = tid >> 5;
    const int wm   = wid & 3;
    const int wn   = wid >> 2;
    const int m0   = blockIdx.y * 128;
    const int n0   = blockIdx.x * 128;

    const size_t Kb = (size_t)K * 2;
    const int NK = K >> 5;

    const char* pAh = (const char*)Ah + (size_t)m0 * Kb;
    const char* pAl = (const char*)Al + (size_t)m0 * Kb;
    const char* pBh = (const char*)Bh + (size_t)n0 * Kb;

    auto load_stage = [&](int kt, int s) {
        const uint32_t sb = sb0 + (uint32_t)s * STB;
        const size_t kb = (size_t)kt * 64;
        #pragma unroll
        for (int i = 0; i < 2; i++) {
            const int c   = tid + i * 256;
            const int row = c >> 2;
            const int seg = (c & 3) * 16;
            const uint32_t so = (uint32_t)(row * RS + seg);
            const size_t go = (size_t)row * Kb + kb + seg;
            cp16(sb + so, pAh + go);
            if (PASSES >= 2) cp16(sb + OFF_AL + so, pAl + go);
            cp16(sb + OFF_BH + so, pBh + go);
        }
    };

    const uint32_t aRow  = (uint32_t)(wm * 32 + (lane & 15));
    const uint32_t aByte = (uint32_t)((lane >> 4) * 16);
    const uint32_t bRow  = (uint32_t)(wn * 64 + (lane & 7) + ((lane >> 4) & 1) * 8);
    const uint32_t bByte = (uint32_t)(((lane >> 3) & 1) * 16);

    float acc[2][8][4] = {};

    #pragma unroll
    for (int s = 0; s < STAGES - 1; s++) { load_stage(s, s); CP_COMMIT(); }

    for (int kt = 0; kt < NK; kt++) {
        asm volatile("cp.async.wait_group %0;" :: "n"(STAGES - 2) : "memory");
        __syncthreads();

        if (kt + STAGES - 1 < NK) load_stage(kt + STAGES - 1, (kt + STAGES - 1) % STAGES);
        CP_COMMIT();

        const uint32_t sb = sb0 + (uint32_t)(kt % STAGES) * STB;

        #pragma unroll
        for (int kk = 0; kk < 2; kk++) {
            uint32_t ah[2][4], al[2][4];
            #pragma unroll
            for (int mi = 0; mi < 2; mi++) {
                const uint32_t ad = sb + (aRow + mi * 16) * RS + kk * 32 + aByte;
                LDSM4(ah[mi][0], ah[mi][1], ah[mi][2], ah[mi][3], ad);
                if (PASSES >= 2)
                    LDSM4(al[mi][0], al[mi][1], al[mi][2], al[mi][3], ad + OFF_AL);
            }
            #pragma unroll
            for (int hf = 0; hf < 2; hf++) {
                uint32_t bh[4][2];
                #pragma unroll
                for (int p = 0; p < 2; p++) {
                    const uint32_t bd = sb + OFF_BH +
                        (bRow + (hf * 2 + p) * 16) * RS + kk * 32 + bByte;
                    uint32_t t0, t1, t2, t3;
                    LDSM4(t0, t1, t2, t3, bd);
                    bh[2 * p][0] = t0; bh[2 * p][1] = t1;
                    bh[2 * p + 1][0] = t2; bh[2 * p + 1][1] = t3;
                }
                #pragma unroll
                for (int mi = 0; mi < 2; mi++)
                    #pragma unroll
                    for (int nj = 0; nj < 4; nj++) {
                        float* d = acc[mi][hf * 4 + nj];
                        MMA_F16(d, ah[mi], bh[nj]);
                        if (PASSES >= 2) MMA_F16(d, al[mi], bh[nj]);
                    }
            }
        }
    }

    const int trow = lane >> 2;
    const int tc   = (lane & 3) * 2;
    #pragma unroll
    for (int mi = 0; mi < 2; mi++) {
        const int r = m0 + wm * 32 + mi * 16 + trow;
        #pragma unroll
        for (int ni = 0; ni < 8; ni++) {
            const int col = n0 + wn * 64 + ni * 8 + tc;
            const float2 bv = *(const float2*)(bias + col);
            const float v00 = acc[mi][ni][0] + bv.x;
            const float v01 = acc[mi][ni][1] + bv.y;
            const float v10 = acc[mi][ni][2] + bv.x;
            const float v11 = acc[mi][ni][3] + bv.y;
            if (MODE == 0) {
                float2 o0 = {v00, v01}, o1 = {v10, v11};
                *(float2*)(C + (size_t)r * Ntot + col) = o0;
                *(float2*)(C + (size_t)(r + 8) * Ntot + col) = o1;
            } else if (MODE == 1) {
                const __half h00 = __float2half_rn(v00);
                const __half h01 = __float2half_rn(v01);
                const __half h10 = __float2half_rn(v10);
                const __half h11 = __float2half_rn(v11);
                *(__half2*)(Ch + (size_t)r * Ntot + col) = __halves2half2(h00, h01);
                *(__half2*)(Cl + (size_t)r * Ntot + col) = __halves2half2(
                    __float2half_rn(v00 - __half2float(h00)),
                    __float2half_rn(v01 - __half2float(h01)));
                *(__half2*)(Ch + (size_t)(r + 8) * Ntot + col) = __halves2half2(h10, h11);
                *(__half2*)(Cl + (size_t)(r + 8) * Ntot + col) = __halves2half2(
                    __float2half_rn(v10 - __half2float(h10)),
                    __float2half_rn(v11 - __half2float(h11)));
            } else {  // MODE 2: fp16 hi only
                *(__half2*)(Ch + (size_t)r * Ntot + col) =
                    __halves2half2(__float2half_rn(v00), __float2half_rn(v01));
                *(__half2*)(Ch + (size_t)(r + 8) * Ntot + col) =
                    __halves2half2(__float2half_rn(v10), __float2half_rn(v11));
            }
        }
    }
}

// smem sizes per instantiation
#define SMEM_P2 (3 * 3 * TILE_B)   // 92160
#define SMEM_P1 (4 * 2 * TILE_B)   // 81920

// ===================== scores via mma (2-pass): (qh+ql) @ kh^T =============
#define RS2 144
#define SC_TILE (128 * RS2)
#define SC_SMEM (3 * SC_TILE)         // 55296

__global__ void __launch_bounds__(256, 2)
scores_tc(const float* __restrict__ prev, const float* __restrict__ scale_p,
          float* __restrict__ scores)
{
    extern __shared__ char dsm[];
    const uint32_t sb = smem_u32(dsm);
    const int tid  = threadIdx.x;
    const int lane = tid & 31;
    const int wid  = tid >> 5;
    const int wm   = wid & 3;
    const int wn   = wid >> 2;
    const int bh = blockIdx.z;
    const int b  = bh >> 4;
    const int h  = bh & 15;
    const int q0 = blockIdx.y * 128;
    const int n0 = blockIdx.x * 128;

    const char* pQh = (const char*)g_qh + ((size_t)(b * Sc + q0) * Dc + h * DKc) * 2;
    const char* pQl = (const char*)g_ql + ((size_t)(b * Sc + q0) * Dc + h * DKc) * 2;
    const char* pKh = (const char*)g_kh + ((size_t)(b * Sc + n0) * Dc + h * DKc) * 2;
    #pragma unroll
    for (int i = 0; i < 4; i++) {
        const int c   = tid + i * 256;
        const int row = c >> 3;
        const int seg = (c & 7) * 16;
        const uint32_t so = (uint32_t)(row * RS2 + seg);
        const size_t go = (size_t)row * (Dc * 2) + seg;
        cp16(sb + so,               pQh + go);
        cp16(sb + SC_TILE + so,     pQl + go);
        cp16(sb + 2 * SC_TILE + so, pKh + go);
    }
    CP_COMMIT(); CP_WAIT0();
    __syncthreads();

    const uint32_t aRow  = (uint32_t)(wm * 32 + (lane & 15));
    const uint32_t aByte = (uint32_t)((lane >> 4) * 16);
    const uint32_t bRow  = (uint32_t)(wn * 64 + (lane & 7) + ((lane >> 4) & 1) * 8);
    const uint32_t bByte = (uint32_t)(((lane >> 3) & 1) * 16);

    float acc[2][8][4] = {};

    #pragma unroll
    for (int kk = 0; kk < 4; kk++) {
        uint32_t ah[2][4], al[2][4];
        #pragma unroll
        for (int mi = 0; mi < 2; mi++) {
            const uint32_t ad = sb + (aRow + mi * 16) * RS2 + kk * 32 + aByte;
            LDSM4(ah[mi][0], ah[mi][1], ah[mi][2], ah[mi][3], ad);
            LDSM4(al[mi][0], al[mi][1], al[mi][2], al[mi][3], ad + SC_TILE);
        }
        #pragma unroll
        for (int hf = 0; hf < 2; hf++) {
            uint32_t bhr[4][2];
            #pragma unroll
            for (int p = 0; p < 2; p++) {
                const uint32_t bd = sb + 2 * SC_TILE +
                    (bRow + (hf * 2 + p) * 16) * RS2 + kk * 32 + bByte;
                uint32_t t0, t1, t2, t3;
                LDSM4(t0, t1, t2, t3, bd);
                bhr[2 * p][0] = t0; bhr[2 * p][1] = t1;
                bhr[2 * p + 1][0] = t2; bhr[2 * p + 1][1] = t3;
            }
            #pragma unroll
            for (int mi = 0; mi < 2; mi++)
                #pragma unroll
                for (int nj = 0; nj < 4; nj++) {
                    float* d = acc[mi][hf * 4 + nj];
                    MMA_F16(d, ah[mi], bhr[nj]);
                    MMA_F16(d, al[mi], bhr[nj]);
                }
        }
    }

    const float scale = *scale_p;
    const int trow = lane >> 2;
    const int tc   = (lane & 3) * 2;
    const size_t base = ((size_t)(b * Hc + h) * Sc) * Sc;
    #pragma unroll
    for (int mi = 0; mi < 2; mi++) {
        const int r = q0 + wm * 32 + mi * 16 + trow;
        #pragma unroll
        for (int ni = 0; ni < 8; ni++) {
            const int col = n0 + wn * 64 + ni * 8 + tc;
            const size_t o0 = base + (size_t)r * Sc + col;
            const size_t o1 = base + (size_t)(r + 8) * Sc + col;
            const float2 p0 = *(const float2*)(prev + o0);
            const float2 p1 = *(const float2*)(prev + o1);
            float2 w0, w1;
            w0.x = fmaf(acc[mi][ni][0], scale, p0.x);
            w0.y = fmaf(acc[mi][ni][1], scale, p0.y);
            w1.x = fmaf(acc[mi][ni][2], scale, p1.x);
            w1.y = fmaf(acc[mi][ni][3], scale, p1.y);
            *(float2*)(scores + o0) = w0;
            *(float2*)(scores + o1) = w1;
        }
    }
}

// ===================== softmax * gate (fp16 gate) ==========================
__global__ void __launch_bounds__(256)
softmax_gate_kernel(float* __restrict__ attn, const float* __restrict__ scores)
{
    const int warp = threadIdx.x >> 5;
    const int lane = threadIdx.x & 31;
    const long long row = (long long)blockIdx.x * 8 + warp;

    const float* srow = scores + row * Sc;
    float*       arow = attn   + row * Sc;

    const int b  = (int)(row >> 13);
    const int hq = (int)(row & 8191);
    const int h  = hq >> 9;
    const int q  = hq & 511;
    const __half* grow = g_gt + (size_t)(b * Sc + q) * Gc + (size_t)h * Sc;

    float4 x[4];
    float mx = -3.402823466e38f;
    #pragma unroll
    for (int t = 0; t < 4; t++) {
        x[t] = *(const float4*)(srow + t * 128 + lane * 4);
        mx = fmaxf(mx, fmaxf(fmaxf(x[t].x, x[t].y), fmaxf(x[t].z, x[t].w)));
    }
    #pragma unroll
    for (int o = 16; o > 0; o >>= 1)
        mx = fmaxf(mx, __shfl_xor_sync(0xffffffffu, mx, o));

    float sum = 0.0f;
    #pragma unroll
    for (int t = 0; t < 4; t++) {
        x[t].x = __expf(x[t].x - mx);
        x[t].y = __expf(x[t].y - mx);
        x[t].z = __expf(x[t].z - mx);
        x[t].w = __expf(x[t].w - mx);
        sum += (x[t].x + x[t].y) + (x[t].z + x[t].w);
    }
    #pragma unroll
    for (int o = 16; o > 0; o >>= 1)
        sum += __shfl_xor_sync(0xffffffffu, sum, o);
    const float inv = 1.0f / sum;

    #pragma unroll
    for (int t = 0; t < 4; t++) {
        const __half2* g2 = (const __half2*)(grow + t * 128 + lane * 4);
        const __half2 ga = g2[0];
        const __half2 gb2 = g2[1];
        float4 o;
        o.x = __low2float(ga)  * x[t].x * inv;
        o.y = __high2float(ga) * x[t].y * inv;
        o.z = __low2float(gb2)  * x[t].z * inv;
        o.w = __high2float(gb2) * x[t].w * inv;
        *(float4*)(arow + t * 128 + lane * 4) = o;
    }
}

// ===================== ctx = attn @ v via mma (1-pass, hi-only out) ========
#define CT_A    (128 * RS2)
#define CT_V    (64 * RS2)
#define CT_SMEM (CT_A + CT_V)   // Ah | Vh  (27648)

__global__ void __launch_bounds__(256, 2)
ctx_tc(const float* __restrict__ attn, __half* __restrict__ Ch)
{
    extern __shared__ char dsm[];
    const uint32_t sA = smem_u32(dsm);
    const uint32_t sV = sA + CT_A;
    const int tid  = threadIdx.x;
    const int lane = tid & 31;
    const int wid  = tid >> 5;
    const int wm   = wid & 3;
    const int wn   = wid >> 2;
    const int bh = blockIdx.y;
    const int b  = bh >> 4;
    const int h  = bh & 15;
    const int q0 = blockIdx.x * 128;

    const size_t abase = ((size_t)(b * Hc + h) * Sc + q0) * Sc;
    const char* pVh = (const char*)g_vh + ((size_t)(b * Sc) * Dc + h * DKc) * 2;

    const uint32_t aRow  = (uint32_t)(wm * 32 + (lane & 15));
    const uint32_t aByte = (uint32_t)((lane >> 4) * 16);
    const uint32_t vRowL = (uint32_t)(lane & 15);
    const uint32_t vColB = (uint32_t)((wn * 32 + (lane >> 4) * 8) * 2);

    float acc[2][4][4] = {};

    for (int kt = 0; kt < 8; kt++) {
        __syncthreads();
        #pragma unroll
        for (int i = 0; i < 2; i++) {
            const int c   = tid + i * 256;
            const int row = c >> 3;
            const int seg = (c & 7) * 16;
            const uint32_t so = (uint32_t)(row * RS2 + seg);
            const size_t go = (size_t)(kt * 64 + row) * (Dc * 2) + seg;
            cp16(sV + so, pVh + go);
        }
        CP_COMMIT();
        // attn tile: 128 rows x 64 fp32 -> fp16 hi in smem
        #pragma unroll
        for (int i = 0; i < 8; i++) {
            const int c   = tid + i * 256;
            const int row = c >> 4;
            const int f4  = c & 15;
            const float4 v = *(const float4*)(attn + abase + (size_t)row * Sc + kt * 64 + f4 * 4);
            const __half2 ph0 = __halves2half2(__float2half_rn(v.x), __float2half_rn(v.y));
            const __half2 ph1 = __halves2half2(__float2half_rn(v.z), __float2half_rn(v.w));
            const uint32_t so = (uint32_t)(row * RS2 + f4 * 8);
            *(uint32_t*)(dsm + (so))     = *(const uint32_t*)&ph0;
            *(uint32_t*)(dsm + (so + 4)) = *(const uint32_t*)&ph1;
        }
        CP_WAIT0();
        __syncthreads();

        #pragma unroll
        for (int kk = 0; kk < 4; kk++) {
            uint32_t ah[2][4];
            #pragma unroll
            for (int mi = 0; mi < 2; mi++) {
                const uint32_t ad = sA + (aRow + mi * 16) * RS2 + kk * 32 + aByte;
                LDSM4(ah[mi][0], ah[mi][1], ah[mi][2], ah[mi][3], ad);
            }
            uint32_t bh_[4][2];
            #pragma unroll
            for (int p = 0; p < 2; p++) {
                const uint32_t vd = sV + (kk * 16 + vRowL) * RS2 + vColB + p * 32;
                uint32_t t0, t1, t2, t3;
                LDSM4T(t0, t1, t2, t3, vd);
                bh_[2 * p][0] = t0; bh_[2 * p][1] = t1;
                bh_[2 * p + 1][0] = t2; bh_[2 * p + 1][1] = t3;
            }
            #pragma unroll
            for (int mi = 0; mi < 2; mi++)
                #pragma unroll
                for (int nj = 0; nj < 4; nj++)
                    MMA_F16(acc[mi][nj], ah[mi], bh_[nj]);
        }
    }

    const int trow = lane >> 2;
    const int tc   = (lane & 3) * 2;
    #pragma unroll
    for (int mi = 0; mi < 2; mi++) {
        const int r = b * Sc + q0 + wm * 32 + mi * 16 + trow;
        #pragma unroll
        for (int nj = 0; nj < 4; nj++) {
            const int col = h * DKc + wn * 32 + nj * 8 + tc;
            *(__half2*)(Ch + (size_t)r * Dc + col) = __halves2half2(
                __float2half_rn(acc[mi][nj][0]), __float2half_rn(acc[mi][nj][1]));
            *(__half2*)(Ch + (size_t)(r + 8) * Dc + col) = __halves2half2(
                __float2half_rn(acc[mi][nj][2]), __float2half_rn(acc[mi][nj][3]));
        }
    }
}

// ---------------------------------------------------------------------------
extern "C" void kernel_launch(void* const* d_in, const int* in_sizes, int n_in,
                              void* d_out, int out_size)
{
    (void)in_sizes; (void)n_in; (void)out_size;

    const float* Q     = (const float*)d_in[0];
    const float* prev  = (const float*)d_in[1];
    const float* Wq    = (const float*)d_in[2];
    const float* bq    = (const float*)d_in[3];
    const float* Wk    = (const float*)d_in[4];
    const float* bk    = (const float*)d_in[5];
    const float* Wv    = (const float*)d_in[6];
    const float* bv    = (const float*)d_in[7];
    const float* Wg    = (const float*)d_in[8];
    const float* bg    = (const float*)d_in[9];
    const float* Wo    = (const float*)d_in[10];
    const float* bo    = (const float*)d_in[11];
    const float* scale = (const float*)d_in[12];

    float* out    = (float*)d_out;
    float* attn   = out + OUT_ELEMS;
    float* scores = attn + ATTN_ELEMS;

    __half *gb, *ah, *al, *wh, *qh, *ql, *kh, *vh;
    cudaGetSymbolAddress((void**)&gb, g_gt);
    cudaGetSymbolAddress((void**)&ah, g_ah);
    cudaGetSymbolAddress((void**)&al, g_al);
    cudaGetSymbolAddress((void**)&wh, g_wh);
    cudaGetSymbolAddress((void**)&qh, g_qh);
    cudaGetSymbolAddress((void**)&ql, g_ql);
    cudaGetSymbolAddress((void**)&kh, g_kh);
    cudaGetSymbolAddress((void**)&vh, g_vh);

    cudaFuncSetAttribute((const void*)gemm_mma<1, 2>, cudaFuncAttributeMaxDynamicSharedMemorySize, SMEM_P2);
    cudaFuncSetAttribute((const void*)gemm_mma<2, 2>, cudaFuncAttributeMaxDynamicSharedMemorySize, SMEM_P2);
    cudaFuncSetAttribute((const void*)gemm_mma<2, 1>, cudaFuncAttributeMaxDynamicSharedMemorySize, SMEM_P1);
    cudaFuncSetAttribute((const void*)gemm_mma<0, 1>, cudaFuncAttributeMaxDynamicSharedMemorySize, SMEM_P1);
    cudaFuncSetAttribute((const void*)scores_tc,      cudaFuncAttributeMaxDynamicSharedMemorySize, SC_SMEM);
    cudaFuncSetAttribute((const void*)ctx_tc,         cudaFuncAttributeMaxDynamicSharedMemorySize, CT_SMEM);

    const dim3 tblk(32, 8);
    const long long nQ4 = (long long)Mc * Dc / 4;

    // split input activations into fp16 hi/lo
    split_kernel<<<(int)(nQ4 / 256), 256>>>(Q, ah, al, nQ4);

    // q projection -> fp16 hi/lo (2-pass)
    transpose_hi<<<dim3(Dc / 32, Dc / 32), tblk>>>(Wq, wh, Dc, Dc);
    gemm_mma<1, 2><<<dim3(Dc / 128, Mc / 128), 256, SMEM_P2>>>(ah, al, wh, bq, nullptr, qh, ql, Dc, Dc);
    // k projection -> fp16 hi only (2-pass)
    transpose_hi<<<dim3(Dc / 32, Dc / 32), tblk>>>(Wk, wh, Dc, Dc);
    gemm_mma<2, 2><<<dim3(Dc / 128, Mc / 128), 256, SMEM_P2>>>(ah, al, wh, bk, nullptr, kh, nullptr, Dc, Dc);
    // v projection -> fp16 hi only (2-pass)
    transpose_hi<<<dim3(Dc / 32, Dc / 32), tblk>>>(Wv, wh, Dc, Dc);
    gemm_mma<2, 2><<<dim3(Dc / 128, Mc / 128), 256, SMEM_P2>>>(ah, al, wh, bv, nullptr, vh, nullptr, Dc, Dc);
    // gate projection (N = 8192) -> fp16, 1-pass
    transpose_hi<<<dim3(Gc / 32, Dc / 32), tblk>>>(Wg, wh, Dc, Gc);
    gemm_mma<2, 1><<<dim3(Gc / 128, Mc / 128), 256, SMEM_P1>>>(ah, nullptr, wh, bg, nullptr, gb, nullptr, Gc, Dc);

    // scores = (qh+ql) kh^T * scale + prev (2-pass)
    scores_tc<<<dim3(4, 4, Bc * Hc), 256, SC_SMEM>>>(prev, scale, scores);
    // attn = gate * softmax(scores)
    softmax_gate_kernel<<<(Bc * Hc * Sc) / 8, 256>>>(attn, scores);
    // ctx = attn @ v (1-pass) -> fp16 hi into ah
    ctx_tc<<<dim3(4, Bc * Hc), 256, CT_SMEM>>>(attn, ah);

    // out = ctx @ Wo + bo (1-pass)
    transpose_hi<<<dim3(Dc / 32, Dc / 32), tblk>>>(Wo, wh, Dc, Dc);
    gemm_mma<0, 1><<<dim3(Dc / 128, Mc / 128), 256, SMEM_P1>>>(ah, nullptr, wh, bo, out, nullptr, nullptr, Dc, Dc);
}

// round 16
// speedup vs baseline: 1.2938x; 1.0858x over previous
#include <cuda_runtime.h>
#include <cuda_fp16.h>
#include <cstdint>
#include <cstddef>

// Problem constants
#define Bc  16
#define Sc  512
#define Dc  1024
#define Hc  16
#define DKc 64
#define Mc  8192   // B*S
#define Gc  8192   // H*S

#define OUT_ELEMS  8388608LL
#define ATTN_ELEMS 67108864LL

// -------------------- device scratch (static globals; no allocs) -----------
__device__ __half g_gt [(size_t)Mc * Gc];     // gate [b*S+s][h*S+k] fp16
__device__ __half g_ah[(size_t)Mc * Dc];      // activation hi / later ctx hi
__device__ __half g_al[(size_t)Mc * Dc];      // activation lo
__device__ __half g_wh[(size_t)Gc * Dc];      // weight^T hi [N,K]
__device__ __half g_qh[(size_t)Mc * Dc];
__device__ __half g_ql[(size_t)Mc * Dc];
__device__ __half g_kh[(size_t)Mc * Dc];
__device__ __half g_vh[(size_t)Mc * Dc];

// ===================== PTX helpers (sm_80-level only) ======================
__device__ __forceinline__ uint32_t smem_u32(const void* p) {
    uint32_t a;
    asm("{ .reg .u64 t; cvta.to.shared.u64 t, %1; cvt.u32.u64 %0, t; }" : "=r"(a) : "l"(p));
    return a;
}
__device__ __forceinline__ void cp16(uint32_t smem, const void* g) {
    asm volatile("cp.async.cg.shared.global [%0], [%1], 16;\n" :: "r"(smem), "l"(g));
}
#define CP_COMMIT() asm volatile("cp.async.commit_group;" ::: "memory")
#define CP_WAIT0()  asm volatile("cp.async.wait_group 0;" ::: "memory")

#define LDSM4(r0, r1, r2, r3, addr) \
    asm volatile("ldmatrix.sync.aligned.m8n8.x4.shared.b16 {%0,%1,%2,%3}, [%4];" \
        : "=r"(r0), "=r"(r1), "=r"(r2), "=r"(r3) : "r"(addr))
#define LDSM4T(r0, r1, r2, r3, addr) \
    asm volatile("ldmatrix.sync.aligned.m8n8.x4.trans.shared.b16 {%0,%1,%2,%3}, [%4];" \
        : "=r"(r0), "=r"(r1), "=r"(r2), "=r"(r3) : "r"(addr))

#define MMA_F16(d, a, b) \
    asm volatile("mma.sync.aligned.m16n8k16.row.col.f32.f16.f16.f32 " \
        "{%0,%1,%2,%3},{%4,%5,%6,%7},{%8,%9},{%0,%1,%2,%3};" \
        : "+f"((d)[0]), "+f"((d)[1]), "+f"((d)[2]), "+f"((d)[3]) \
        : "r"((a)[0]), "r"((a)[1]), "r"((a)[2]), "r"((a)[3]), \
          "r"((b)[0]), "r"((b)[1]))

// ===================== conversion kernels ==================================
__global__ void __launch_bounds__(256)
split_kernel(const float* __restrict__ x, __half* __restrict__ hi,
             __half* __restrict__ lo, long long n4)
{
    long long i = ((long long)blockIdx.x * 256 + threadIdx.x);
    if (i >= n4) return;
    const float4 v = ((const float4*)x)[i];
    const __half h0 = __float2half_rn(v.x);
    const __half h1 = __float2half_rn(v.y);
    const __half h2 = __float2half_rn(v.z);
    const __half h3 = __float2half_rn(v.w);
    ((__half2*)hi)[i * 2 + 0] = __halves2half2(h0, h1);
    ((__half2*)hi)[i * 2 + 1] = __halves2half2(h2, h3);
    ((__half2*)lo)[i * 2 + 0] = __halves2half2(
        __float2half_rn(v.x - __half2float(h0)),
        __float2half_rn(v.y - __half2float(h1)));
    ((__half2*)lo)[i * 2 + 1] = __halves2half2(
        __float2half_rn(v.z - __half2float(h2)),
        __float2half_rn(v.w - __half2float(h3)));
}

// W[K][N] fp32 -> T[N][K] fp16 hi only
__global__ void __launch_bounds__(256)
transpose_hi(const float* __restrict__ W, __half* __restrict__ Th, int K, int N)
{
    __shared__ float t[32][33];
    const int n0 = blockIdx.x * 32, k0 = blockIdx.y * 32;
    const int tx = threadIdx.x, ty = threadIdx.y;  // (32, 8)
    #pragma unroll
    for (int p = 0; p < 4; p++) {
        const int kk = ty + p * 8;
        t[kk][tx] = W[(size_t)(k0 + kk) * N + n0 + tx];
    }
    __syncthreads();
    #pragma unroll
    for (int p = 0; p < 4; p++) {
        const int nn = ty + p * 8;
        Th[(size_t)(n0 + nn) * K + k0 + tx] = __float2half_rn(t[tx][nn]);
    }
}

// ===================== mma.sync split-fp16 GEMM (multi-stage) ==============
// PASSES==2: Ah@Bh + Al@Bh (3 tiles/stage, 3 stages).
// PASSES==1: Ah@Bh         (2 tiles/stage, 4 stages).
// MODE 0: C fp32 (+bias). MODE 1: fp16 hi/lo split. MODE 2: fp16 hi only.
#define RS 80
#define TILE_B   (128 * RS)

template<int MODE, int PASSES>
__global__ void __launch_bounds__(256, 2)
gemm_mma(const __half* __restrict__ Ah, const __half* __restrict__ Al,
         const __half* __restrict__ Bh,
         const float* __restrict__ bias, float* __restrict__ C,
         __half* __restrict__ Ch, __half* __restrict__ Cl,
         int Ntot, int K)
{
    constexpr int TILES  = (PASSES == 2) ? 3 : 2;
    constexpr int STAGES = (PASSES == 2) ? 3 : 4;
    constexpr uint32_t STB    = (uint32_t)TILES * TILE_B;
    constexpr uint32_t OFF_AL = TILE_B;                            // PASSES==2
    constexpr uint32_t OFF_BH = (PASSES >= 2 ? 2u : 1u) * TILE_B;

    extern __shared__ char dsm[];
    const uint32_t sb0 = smem_u32(dsm);
    const int tid  = threadIdx.x;
    const int lane = tid & 31;
    const int wid  = tid >> 5;
    const int wm   = wid & 3;
    const int wn   = wid >> 2;
    const int m0   = blockIdx.y * 128;
    const int n0   = blockIdx.x * 128;

    const size_t Kb = (size_t)K * 2;
    const int NK = K >> 5;

    const char* pAh = (const char*)Ah + (size_t)m0 * Kb;
    const char* pAl = (const char*)Al + (size_t)m0 * Kb;
    const char* pBh = (const char*)Bh + (size_t)n0 * Kb;

    auto load_stage = [&](int kt, int s) {
        const uint32_t sb = sb0 + (uint32_t)s * STB;
        const size_t kb = (size_t)kt * 64;
        #pragma unroll
        for (int i = 0; i < 2; i++) {
            const int c   = tid + i * 256;
            const int row = c >> 2;
            const int seg = (c & 3) * 16;
            const uint32_t so = (uint32_t)(row * RS + seg);
            const size_t go = (size_t)row * Kb + kb + seg;
            cp16(sb + so, pAh + go);
            if (PASSES >= 2) cp16(sb + OFF_AL + so, pAl + go);
            cp16(sb + OFF_BH + so, pBh + go);
        }
    };

    const uint32_t aRow  = (uint32_t)(wm * 32 + (lane & 15));
    const uint32_t aByte = (uint32_t)((lane >> 4) * 16);
    const uint32_t bRow  = (uint32_t)(wn * 64 + (lane & 7) + ((lane >> 4) & 1) * 8);
    const uint32_t bByte = (uint32_t)(((lane >> 3) & 1) * 16);

    float acc[2][8][4] = {};

    #pragma unroll
    for (int s = 0; s < STAGES - 1; s++) { load_stage(s, s); CP_COMMIT(); }

    for (int kt = 0; kt < NK; kt++) {
        asm volatile("cp.async.wait_group %0;" :: "n"(STAGES - 2) : "memory");
        __syncthreads();

        if (kt + STAGES - 1 < NK) load_stage(kt + STAGES - 1, (kt + STAGES - 1) % STAGES);
        CP_COMMIT();

        const uint32_t sb = sb0 + (uint32_t)(kt % STAGES) * STB;

        #pragma unroll
        for (int kk = 0; kk < 2; kk++) {
            uint32_t ah[2][4], al[2][4];
            #pragma unroll
            for (int mi = 0; mi < 2; mi++) {
                const uint32_t ad = sb + (aRow + mi * 16) * RS + kk * 32 + aByte;
                LDSM4(ah[mi][0], ah[mi][1], ah[mi][2], ah[mi][3], ad);
                if (PASSES >= 2)
                    LDSM4(al[mi][0], al[mi][1], al[mi][2], al[mi][3], ad + OFF_AL);
            }
            #pragma unroll
            for (int hf = 0; hf < 2; hf++) {
                uint32_t bh[4][2];
                #pragma unroll
                for (int p = 0; p < 2; p++) {
                    const uint32_t bd = sb + OFF_BH +
                        (bRow + (hf * 2 + p) * 16) * RS + kk * 32 + bByte;
                    uint32_t t0, t1, t2, t3;
                    LDSM4(t0, t1, t2, t3, bd);
                    bh[2 * p][0] = t0; bh[2 * p][1] = t1;
                    bh[2 * p + 1][0] = t2; bh[2 * p + 1][1] = t3;
                }
                #pragma unroll
                for (int mi = 0; mi < 2; mi++)
                    #pragma unroll
                    for (int nj = 0; nj < 4; nj++) {
                        float* d = acc[mi][hf * 4 + nj];
                        MMA_F16(d, ah[mi], bh[nj]);
                        if (PASSES >= 2) MMA_F16(d, al[mi], bh[nj]);
                    }
            }
        }
    }

    const int trow = lane >> 2;
    const int tc   = (lane & 3) * 2;
    #pragma unroll
    for (int mi = 0; mi < 2; mi++) {
        const int r = m0 + wm * 32 + mi * 16 + trow;
        #pragma unroll
        for (int ni = 0; ni < 8; ni++) {
            const int col = n0 + wn * 64 + ni * 8 + tc;
            const float2 bv = *(const float2*)(bias + col);
            const float v00 = acc[mi][ni][0] + bv.x;
            const float v01 = acc[mi][ni][1] + bv.y;
            const float v10 = acc[mi][ni][2] + bv.x;
            const float v11 = acc[mi][ni][3] + bv.y;
            if (MODE == 0) {
                float2 o0 = {v00, v01}, o1 = {v10, v11};
                *(float2*)(C + (size_t)r * Ntot + col) = o0;
                *(float2*)(C + (size_t)(r + 8) * Ntot + col) = o1;
            } else if (MODE == 1) {
                const __half h00 = __float2half_rn(v00);
                const __half h01 = __float2half_rn(v01);
                const __half h10 = __float2half_rn(v10);
                const __half h11 = __float2half_rn(v11);
                *(__half2*)(Ch + (size_t)r * Ntot + col) = __halves2half2(h00, h01);
                *(__half2*)(Cl + (size_t)r * Ntot + col) = __halves2half2(
                    __float2half_rn(v00 - __half2float(h00)),
                    __float2half_rn(v01 - __half2float(h01)));
                *(__half2*)(Ch + (size_t)(r + 8) * Ntot + col) = __halves2half2(h10, h11);
                *(__half2*)(Cl + (size_t)(r + 8) * Ntot + col) = __halves2half2(
                    __float2half_rn(v10 - __half2float(h10)),
                    __float2half_rn(v11 - __half2float(h11)));
            } else {  // MODE 2: fp16 hi only
                *(__half2*)(Ch + (size_t)r * Ntot + col) =
                    __halves2half2(__float2half_rn(v00), __float2half_rn(v01));
                *(__half2*)(Ch + (size_t)(r + 8) * Ntot + col) =
                    __halves2half2(__float2half_rn(v10), __float2half_rn(v11));
            }
        }
    }
}

// smem sizes per instantiation
#define SMEM_P2 (3 * 3 * TILE_B)   // 92160
#define SMEM_P1 (4 * 2 * TILE_B)   // 81920

// ===================== scores via mma (2-pass): (qh+ql) @ kh^T =============
#define RS2 144
#define SC_TILE (128 * RS2)
#define SC_SMEM (3 * SC_TILE)         // 55296

__global__ void __launch_bounds__(256, 2)
scores_tc(const float* __restrict__ prev, const float* __restrict__ scale_p,
          float* __restrict__ scores)
{
    extern __shared__ char dsm[];
    const uint32_t sb = smem_u32(dsm);
    const int tid  = threadIdx.x;
    const int lane = tid & 31;
    const int wid  = tid >> 5;
    const int wm   = wid & 3;
    const int wn   = wid >> 2;
    const int bh = blockIdx.z;
    const int b  = bh >> 4;
    const int h  = bh & 15;
    const int q0 = blockIdx.y * 128;
    const int n0 = blockIdx.x * 128;

    const char* pQh = (const char*)g_qh + ((size_t)(b * Sc + q0) * Dc + h * DKc) * 2;
    const char* pQl = (const char*)g_ql + ((size_t)(b * Sc + q0) * Dc + h * DKc) * 2;
    const char* pKh = (const char*)g_kh + ((size_t)(b * Sc + n0) * Dc + h * DKc) * 2;
    #pragma unroll
    for (int i = 0; i < 4; i++) {
        const int c   = tid + i * 256;
        const int row = c >> 3;
        const int seg = (c & 7) * 16;
        const uint32_t so = (uint32_t)(row * RS2 + seg);
        const size_t go = (size_t)row * (Dc * 2) + seg;
        cp16(sb + so,               pQh + go);
        cp16(sb + SC_TILE + so,     pQl + go);
        cp16(sb + 2 * SC_TILE + so, pKh + go);
    }
    CP_COMMIT(); CP_WAIT0();
    __syncthreads();

    const uint32_t aRow  = (uint32_t)(wm * 32 + (lane & 15));
    const uint32_t aByte = (uint32_t)((lane >> 4) * 16);
    const uint32_t bRow  = (uint32_t)(wn * 64 + (lane & 7) + ((lane >> 4) & 1) * 8);
    const uint32_t bByte = (uint32_t)(((lane >> 3) & 1) * 16);

    float acc[2][8][4] = {};

    #pragma unroll
    for (int kk = 0; kk < 4; kk++) {
        uint32_t ah[2][4], al[2][4];
        #pragma unroll
        for (int mi = 0; mi < 2; mi++) {
            const uint32_t ad = sb + (aRow + mi * 16) * RS2 + kk * 32 + aByte;
            LDSM4(ah[mi][0], ah[mi][1], ah[mi][2], ah[mi][3], ad);
            LDSM4(al[mi][0], al[mi][1], al[mi][2], al[mi][3], ad + SC_TILE);
        }
        #pragma unroll
        for (int hf = 0; hf < 2; hf++) {
            uint32_t bhr[4][2];
            #pragma unroll
            for (int p = 0; p < 2; p++) {
                const uint32_t bd = sb + 2 * SC_TILE +
                    (bRow + (hf * 2 + p) * 16) * RS2 + kk * 32 + bByte;
                uint32_t t0, t1, t2, t3;
                LDSM4(t0, t1, t2, t3, bd);
                bhr[2 * p][0] = t0; bhr[2 * p][1] = t1;
                bhr[2 * p + 1][0] = t2; bhr[2 * p + 1][1] = t3;
            }
            #pragma unroll
            for (int mi = 0; mi < 2; mi++)
                #pragma unroll
                for (int nj = 0; nj < 4; nj++) {
                    float* d = acc[mi][hf * 4 + nj];
                    MMA_F16(d, ah[mi], bhr[nj]);
                    MMA_F16(d, al[mi], bhr[nj]);
                }
        }
    }

    const float scale = *scale_p;
    const int trow = lane >> 2;
    const int tc   = (lane & 3) * 2;
    const size_t base = ((size_t)(b * Hc + h) * Sc) * Sc;
    #pragma unroll
    for (int mi = 0; mi < 2; mi++) {
        const int r = q0 + wm * 32 + mi * 16 + trow;
        #pragma unroll
        for (int ni = 0; ni < 8; ni++) {
            const int col = n0 + wn * 64 + ni * 8 + tc;
            const size_t o0 = base + (size_t)r * Sc + col;
            const size_t o1 = base + (size_t)(r + 8) * Sc + col;
            const float2 p0 = *(const float2*)(prev + o0);
            const float2 p1 = *(const float2*)(prev + o1);
            float2 w0, w1;
            w0.x = fmaf(acc[mi][ni][0], scale, p0.x);
            w0.y = fmaf(acc[mi][ni][1], scale, p0.y);
            w1.x = fmaf(acc[mi][ni][2], scale, p1.x);
            w1.y = fmaf(acc[mi][ni][3], scale, p1.y);
            *(float2*)(scores + o0) = w0;
            *(float2*)(scores + o1) = w1;
        }
    }
}

// ===================== softmax * gate (fp16 gate) ==========================
__global__ void __launch_bounds__(256)
softmax_gate_kernel(float* __restrict__ attn, const float* __restrict__ scores)
{
    const int warp = threadIdx.x >> 5;
    const int lane = threadIdx.x & 31;
    const long long row = (long long)blockIdx.x * 8 + warp;

    const float* srow = scores + row * Sc;
    float*       arow = attn   + row * Sc;

    const int b  = (int)(row >> 13);
    const int hq = (int)(row & 8191);
    const int h  = hq >> 9;
    const int q  = hq & 511;
    const __half* grow = g_gt + (size_t)(b * Sc + q) * Gc + (size_t)h * Sc;

    float4 x[4];
    float mx = -3.402823466e38f;
    #pragma unroll
    for (int t = 0; t < 4; t++) {
        x[t] = *(const float4*)(srow + t * 128 + lane * 4);
        mx = fmaxf(mx, fmaxf(fmaxf(x[t].x, x[t].y), fmaxf(x[t].z, x[t].w)));
    }
    #pragma unroll
    for (int o = 16; o > 0; o >>= 1)
        mx = fmaxf(mx, __shfl_xor_sync(0xffffffffu, mx, o));

    float sum = 0.0f;
    #pragma unroll
    for (int t = 0; t < 4; t++) {
        x[t].x = __expf(x[t].x - mx);
        x[t].y = __expf(x[t].y - mx);
        x[t].z = __expf(x[t].z - mx);
        x[t].w = __expf(x[t].w - mx);
        sum += (x[t].x + x[t].y) + (x[t].z + x[t].w);
    }
    #pragma unroll
    for (int o = 16; o > 0; o >>= 1)
        sum += __shfl_xor_sync(0xffffffffu, sum, o);
    const float inv = 1.0f / sum;

    #pragma unroll
    for (int t = 0; t < 4; t++) {
        const __half2* g2 = (const __half2*)(grow + t * 128 + lane * 4);
        const __half2 ga = g2[0];
        const __half2 gb2 = g2[1];
        float4 o;
        o.x = __low2float(ga)  * x[t].x * inv;
        o.y = __high2float(ga) * x[t].y * inv;
        o.z = __low2float(gb2)  * x[t].z * inv;
        o.w = __high2float(gb2) * x[t].w * inv;
        *(float4*)(arow + t * 128 + lane * 4) = o;
    }
}

// ===================== ctx = attn @ v via mma (1-pass, hi-only out) ========
#define CT_A    (128 * RS2)
#define CT_V    (64 * RS2)
#define CT_SMEM (CT_A + CT_V)   // Ah | Vh  (27648)

__global__ void __launch_bounds__(256, 2)
ctx_tc(const float* __restrict__ attn, __half* __restrict__ Ch)
{
    extern __shared__ char dsm[];
    const uint32_t sA = smem_u32(dsm);
    const uint32_t sV = sA + CT_A;
    const int tid  = threadIdx.x;
    const int lane = tid & 31;
    const int wid  = tid >> 5;
    const int wm   = wid & 3;
    const int wn   = wid >> 2;
    const int bh = blockIdx.y;
    const int b  = bh >> 4;
    const int h  = bh & 15;
    const int q0 = blockIdx.x * 128;

    const size_t abase = ((size_t)(b * Hc + h) * Sc + q0) * Sc;
    const char* pVh = (const char*)g_vh + ((size_t)(b * Sc) * Dc + h * DKc) * 2;

    const uint32_t aRow  = (uint32_t)(wm * 32 + (lane & 15));
    const uint32_t aByte = (uint32_t)((lane >> 4) * 16);
    const uint32_t vRowL = (uint32_t)(lane & 15);
    const uint32_t vColB = (uint32_t)((wn * 32 + (lane >> 4) * 8) * 2);

    float acc[2][4][4] = {};

    for (int kt = 0; kt < 8; kt++) {
        __syncthreads();
        #pragma unroll
        for (int i = 0; i < 2; i++) {
            const int c   = tid + i * 256;
            const int row = c >> 3;
            const int seg = (c & 7) * 16;
            const uint32_t so = (uint32_t)(row * RS2 + seg);
            const size_t go = (size_t)(kt * 64 + row) * (Dc * 2) + seg;
            cp16(sV + so, pVh + go);
        }
        CP_COMMIT();
        // attn tile: 128 rows x 64 fp32 -> fp16 hi in smem
        #pragma unroll
        for (int i = 0; i < 8; i++) {
            const int c   = tid + i * 256;
            const int row = c >> 4;
            const int f4  = c & 15;
            const float4 v = *(const float4*)(attn + abase + (size_t)row * Sc + kt * 64 + f4 * 4);
            const __half2 ph0 = __halves2half2(__float2half_rn(v.x), __float2half_rn(v.y));
            const __half2 ph1 = __halves2half2(__float2half_rn(v.z), __float2half_rn(v.w));
            const uint32_t so = (uint32_t)(row * RS2 + f4 * 8);
            *(uint32_t*)(dsm + (so))     = *(const uint32_t*)&ph0;
            *(uint32_t*)(dsm + (so + 4)) = *(const uint32_t*)&ph1;
        }
        CP_WAIT0();
        __syncthreads();

        #pragma unroll
        for (int kk = 0; kk < 4; kk++) {
            uint32_t ah[2][4];
            #pragma unroll
            for (int mi = 0; mi < 2; mi++) {
                const uint32_t ad = sA + (aRow + mi * 16) * RS2 + kk * 32 + aByte;
                LDSM4(ah[mi][0], ah[mi][1], ah[mi][2], ah[mi][3], ad);
            }
            uint32_t bh_[4][2];
            #pragma unroll
            for (int p = 0; p < 2; p++) {
                const uint32_t vd = sV + (kk * 16 + vRowL) * RS2 + vColB + p * 32;
                uint32_t t0, t1, t2, t3;
                LDSM4T(t0, t1, t2, t3, vd);
                bh_[2 * p][0] = t0; bh_[2 * p][1] = t1;
                bh_[2 * p + 1][0] = t2; bh_[2 * p + 1][1] = t3;
            }
            #pragma unroll
            for (int mi = 0; mi < 2; mi++)
                #pragma unroll
                for (int nj = 0; nj < 4; nj++)
                    MMA_F16(acc[mi][nj], ah[mi], bh_[nj]);
        }
    }

    const int trow = lane >> 2;
    const int tc   = (lane & 3) * 2;
    #pragma unroll
    for (int mi = 0; mi < 2; mi++) {
        const int r = b * Sc + q0 + wm * 32 + mi * 16 + trow;
        #pragma unroll
        for (int nj = 0; nj < 4; nj++) {
            const int col = h * DKc + wn * 32 + nj * 8 + tc;
            *(__half2*)(Ch + (size_t)r * Dc + col) = __halves2half2(
                __float2half_rn(acc[mi][nj][0]), __float2half_rn(acc[mi][nj][1]));
            *(__half2*)(Ch + (size_t)(r + 8) * Dc + col) = __halves2half2(
                __float2half_rn(acc[mi][nj][2]), __float2half_rn(acc[mi][nj][3]));
        }
    }
}

// ---------------------------------------------------------------------------
extern "C" void kernel_launch(void* const* d_in, const int* in_sizes, int n_in,
                              void* d_out, int out_size)
{
    (void)in_sizes; (void)n_in; (void)out_size;

    const float* Q     = (const float*)d_in[0];
    const float* prev  = (const float*)d_in[1];
    const float* Wq    = (const float*)d_in[2];
    const float* bq    = (const float*)d_in[3];
    const float* Wk    = (const float*)d_in[4];
    const float* bk    = (const float*)d_in[5];
    const float* Wv    = (const float*)d_in[6];
    const float* bv    = (const float*)d_in[7];
    const float* Wg    = (const float*)d_in[8];
    const float* bg    = (const float*)d_in[9];
    const float* Wo    = (const float*)d_in[10];
    const float* bo    = (const float*)d_in[11];
    const float* scale = (const float*)d_in[12];

    float* out    = (float*)d_out;
    float* attn   = out + OUT_ELEMS;
    float* scores = attn + ATTN_ELEMS;

    __half *gb, *ah, *al, *wh, *qh, *ql, *kh, *vh;
    cudaGetSymbolAddress((void**)&gb, g_gt);
    cudaGetSymbolAddress((void**)&ah, g_ah);
    cudaGetSymbolAddress((void**)&al, g_al);
    cudaGetSymbolAddress((void**)&wh, g_wh);
    cudaGetSymbolAddress((void**)&qh, g_qh);
    cudaGetSymbolAddress((void**)&ql, g_ql);
    cudaGetSymbolAddress((void**)&kh, g_kh);
    cudaGetSymbolAddress((void**)&vh, g_vh);

    cudaFuncSetAttribute((const void*)gemm_mma<1, 2>, cudaFuncAttributeMaxDynamicSharedMemorySize, SMEM_P2);
    cudaFuncSetAttribute((const void*)gemm_mma<2, 1>, cudaFuncAttributeMaxDynamicSharedMemorySize, SMEM_P1);
    cudaFuncSetAttribute((const void*)gemm_mma<0, 1>, cudaFuncAttributeMaxDynamicSharedMemorySize, SMEM_P1);
    cudaFuncSetAttribute((const void*)scores_tc,      cudaFuncAttributeMaxDynamicSharedMemorySize, SC_SMEM);
    cudaFuncSetAttribute((const void*)ctx_tc,         cudaFuncAttributeMaxDynamicSharedMemorySize, CT_SMEM);

    const dim3 tblk(32, 8);
    const long long nQ4 = (long long)Mc * Dc / 4;

    // split input activations into fp16 hi/lo
    split_kernel<<<(int)(nQ4 / 256), 256>>>(Q, ah, al, nQ4);

    // q projection -> fp16 hi/lo (2-pass; feeds scores, highest-volume output)
    transpose_hi<<<dim3(Dc / 32, Dc / 32), tblk>>>(Wq, wh, Dc, Dc);
    gemm_mma<1, 2><<<dim3(Dc / 128, Mc / 128), 256, SMEM_P2>>>(ah, al, wh, bq, nullptr, qh, ql, Dc, Dc);
    // k projection -> fp16 hi only (1-pass)
    transpose_hi<<<dim3(Dc / 32, Dc / 32), tblk>>>(Wk, wh, Dc, Dc);
    gemm_mma<2, 1><<<dim3(Dc / 128, Mc / 128), 256, SMEM_P1>>>(ah, nullptr, wh, bk, nullptr, kh, nullptr, Dc, Dc);
    // v projection -> fp16 hi only (1-pass)
    transpose_hi<<<dim3(Dc / 32, Dc / 32), tblk>>>(Wv, wh, Dc, Dc);
    gemm_mma<2, 1><<<dim3(Dc / 128, Mc / 128), 256, SMEM_P1>>>(ah, nullptr, wh, bv, nullptr, vh, nullptr, Dc, Dc);
    // gate projection (N = 8192) -> fp16, 1-pass
    transpose_hi<<<dim3(Gc / 32, Dc / 32), tblk>>>(Wg, wh, Dc, Gc);
    gemm_mma<2, 1><<<dim3(Gc / 128, Mc / 128), 256, SMEM_P1>>>(ah, nullptr, wh, bg, nullptr, gb, nullptr, Gc, Dc);

    // scores = (qh+ql) kh^T * scale + prev (2-pass)
    scores_tc<<<dim3(4, 4, Bc * Hc), 256, SC_SMEM>>>(prev, scale, scores);
    // attn = gate * softmax(scores)
    softmax_gate_kernel<<<(Bc * Hc * Sc) / 8, 256>>>(attn, scores);
    // ctx = attn @ v (1-pass) -> fp16 hi into ah
    ctx_tc<<<dim3(4, Bc * Hc), 256, CT_SMEM>>>(attn, ah);

    // out = ctx @ Wo + bo (1-pass)
    transpose_hi<<<dim3(Dc / 32, Dc / 32), tblk>>>(Wo, wh, Dc, Dc);
    gemm_mma<0, 1><<<dim3(Dc / 128, Mc / 128), 256, SMEM_P1>>>(ah, nullptr, wh, bo, out, nullptr, nullptr, Dc, Dc);
}

// round 17
// speedup vs baseline: 1.3795x; 1.0662x over previous
#include <cuda_runtime.h>
#include <cuda_fp16.h>
#include <cstdint>
#include <cstddef>

// Problem constants
#define Bc  16
#define Sc  512
#define Dc  1024
#define Hc  16
#define DKc 64
#define Mc  8192   // B*S
#define Gc  8192   // H*S

#define OUT_ELEMS  8388608LL
#define ATTN_ELEMS 67108864LL

// -------------------- device scratch (static globals; no allocs) -----------
__device__ __half g_gt [(size_t)Mc * Gc];     // gate [b*S+s][h*S+k] fp16
__device__ __half g_ah[(size_t)Mc * Dc];      // activation hi / later ctx hi
__device__ __half g_wh[(size_t)Gc * Dc];      // weight^T hi [N,K]
__device__ __half g_qh[(size_t)Mc * Dc];
__device__ __half g_kh[(size_t)Mc * Dc];
__device__ __half g_vh[(size_t)Mc * Dc];

// ===================== PTX helpers (sm_80-level only) ======================
__device__ __forceinline__ uint32_t smem_u32(const void* p) {
    uint32_t a;
    asm("{ .reg .u64 t; cvta.to.shared.u64 t, %1; cvt.u32.u64 %0, t; }" : "=r"(a) : "l"(p));
    return a;
}
__device__ __forceinline__ void cp16(uint32_t smem, const void* g) {
    asm volatile("cp.async.cg.shared.global [%0], [%1], 16;\n" :: "r"(smem), "l"(g));
}
#define CP_COMMIT() asm volatile("cp.async.commit_group;" ::: "memory")
#define CP_WAIT0()  asm volatile("cp.async.wait_group 0;" ::: "memory")

#define LDSM4(r0, r1, r2, r3, addr) \
    asm volatile("ldmatrix.sync.aligned.m8n8.x4.shared.b16 {%0,%1,%2,%3}, [%4];" \
        : "=r"(r0), "=r"(r1), "=r"(r2), "=r"(r3) : "r"(addr))
#define LDSM4T(r0, r1, r2, r3, addr) \
    asm volatile("ldmatrix.sync.aligned.m8n8.x4.trans.shared.b16 {%0,%1,%2,%3}, [%4];" \
        : "=r"(r0), "=r"(r1), "=r"(r2), "=r"(r3) : "r"(addr))

#define MMA_F16(d, a, b) \
    asm volatile("mma.sync.aligned.m16n8k16.row.col.f32.f16.f16.f32 " \
        "{%0,%1,%2,%3},{%4,%5,%6,%7},{%8,%9},{%0,%1,%2,%3};" \
        : "+f"((d)[0]), "+f"((d)[1]), "+f"((d)[2]), "+f"((d)[3]) \
        : "r"((a)[0]), "r"((a)[1]), "r"((a)[2]), "r"((a)[3]), \
          "r"((b)[0]), "r"((b)[1]))

// ===================== conversion kernels ==================================
__global__ void __launch_bounds__(256)
split_hi_kernel(const float* __restrict__ x, __half* __restrict__ hi, long long n4)
{
    long long i = ((long long)blockIdx.x * 256 + threadIdx.x);
    if (i >= n4) return;
    const float4 v = ((const float4*)x)[i];
    ((__half2*)hi)[i * 2 + 0] = __halves2half2(__float2half_rn(v.x), __float2half_rn(v.y));
    ((__half2*)hi)[i * 2 + 1] = __halves2half2(__float2half_rn(v.z), __float2half_rn(v.w));
}

// W[K][N] fp32 -> T[N][K] fp16 hi only
__global__ void __launch_bounds__(256)
transpose_hi(const float* __restrict__ W, __half* __restrict__ Th, int K, int N)
{
    __shared__ float t[32][33];
    const int n0 = blockIdx.x * 32, k0 = blockIdx.y * 32;
    const int tx = threadIdx.x, ty = threadIdx.y;  // (32, 8)
    #pragma unroll
    for (int p = 0; p < 4; p++) {
        const int kk = ty + p * 8;
        t[kk][tx] = W[(size_t)(k0 + kk) * N + n0 + tx];
    }
    __syncthreads();
    #pragma unroll
    for (int p = 0; p < 4; p++) {
        const int nn = ty + p * 8;
        Th[(size_t)(n0 + nn) * K + k0 + tx] = __float2half_rn(t[tx][nn]);
    }
}

// ===================== mma.sync fp16 GEMM (1-pass, 4-stage pipeline) =======
// C = Ah @ Bh^T. MODE 0: C fp32 (+bias). MODE 2: fp16 hi only.
#define RS 80
#define TILE_B   (128 * RS)
#define STAGES   4
#define STB      (2u * TILE_B)
#define OFF_BH   TILE_B
#define GEMM_SMEM (STAGES * 2 * TILE_B)   // 81920

template<int MODE>
__global__ void __launch_bounds__(256, 2)
gemm_mma(const __half* __restrict__ Ah, const __half* __restrict__ Bh,
         const float* __restrict__ bias, float* __restrict__ C,
         __half* __restrict__ Ch, int Ntot, int K)
{
    extern __shared__ char dsm[];
    const uint32_t sb0 = smem_u32(dsm);
    const int tid  = threadIdx.x;
    const int lane = tid & 31;
    const int wid  = tid >> 5;
    const int wm   = wid & 3;
    const int wn   = wid >> 2;
    const int m0   = blockIdx.y * 128;
    const int n0   = blockIdx.x * 128;

    const size_t Kb = (size_t)K * 2;
    const int NK = K >> 5;

    const char* pAh = (const char*)Ah + (size_t)m0 * Kb;
    const char* pBh = (const char*)Bh + (size_t)n0 * Kb;

    auto load_stage = [&](int kt, int s) {
        const uint32_t sb = sb0 + (uint32_t)s * STB;
        const size_t kb = (size_t)kt * 64;
        #pragma unroll
        for (int i = 0; i < 2; i++) {
            const int c   = tid + i * 256;
            const int row = c >> 2;
            const int seg = (c & 3) * 16;
            const uint32_t so = (uint32_t)(row * RS + seg);
            const size_t go = (size_t)row * Kb + kb + seg;
            cp16(sb + so, pAh + go);
            cp16(sb + OFF_BH + so, pBh + go);
        }
    };

    const uint32_t aRow  = (uint32_t)(wm * 32 + (lane & 15));
    const uint32_t aByte = (uint32_t)((lane >> 4) * 16);
    const uint32_t bRow  = (uint32_t)(wn * 64 + (lane & 7) + ((lane >> 4) & 1) * 8);
    const uint32_t bByte = (uint32_t)(((lane >> 3) & 1) * 16);

    float acc[2][8][4] = {};

    #pragma unroll
    for (int s = 0; s < STAGES - 1; s++) { load_stage(s, s); CP_COMMIT(); }

    for (int kt = 0; kt < NK; kt++) {
        asm volatile("cp.async.wait_group %0;" :: "n"(STAGES - 2) : "memory");
        __syncthreads();

        if (kt + STAGES - 1 < NK) load_stage(kt + STAGES - 1, (kt + STAGES - 1) % STAGES);
        CP_COMMIT();

        const uint32_t sb = sb0 + (uint32_t)(kt % STAGES) * STB;

        #pragma unroll
        for (int kk = 0; kk < 2; kk++) {
            uint32_t ah[2][4];
            #pragma unroll
            for (int mi = 0; mi < 2; mi++) {
                const uint32_t ad = sb + (aRow + mi * 16) * RS + kk * 32 + aByte;
                LDSM4(ah[mi][0], ah[mi][1], ah[mi][2], ah[mi][3], ad);
            }
            #pragma unroll
            for (int hf = 0; hf < 2; hf++) {
                uint32_t bh[4][2];
                #pragma unroll
                for (int p = 0; p < 2; p++) {
                    const uint32_t bd = sb + OFF_BH +
                        (bRow + (hf * 2 + p) * 16) * RS + kk * 32 + bByte;
                    uint32_t t0, t1, t2, t3;
                    LDSM4(t0, t1, t2, t3, bd);
                    bh[2 * p][0] = t0; bh[2 * p][1] = t1;
                    bh[2 * p + 1][0] = t2; bh[2 * p + 1][1] = t3;
                }
                #pragma unroll
                for (int mi = 0; mi < 2; mi++)
                    #pragma unroll
                    for (int nj = 0; nj < 4; nj++)
                        MMA_F16(acc[mi][hf * 4 + nj], ah[mi], bh[nj]);
            }
        }
    }

    const int trow = lane >> 2;
    const int tc   = (lane & 3) * 2;
    #pragma unroll
    for (int mi = 0; mi < 2; mi++) {
        const int r = m0 + wm * 32 + mi * 16 + trow;
        #pragma unroll
        for (int ni = 0; ni < 8; ni++) {
            const int col = n0 + wn * 64 + ni * 8 + tc;
            const float2 bv = *(const float2*)(bias + col);
            const float v00 = acc[mi][ni][0] + bv.x;
            const float v01 = acc[mi][ni][1] + bv.y;
            const float v10 = acc[mi][ni][2] + bv.x;
            const float v11 = acc[mi][ni][3] + bv.y;
            if (MODE == 0) {
                float2 o0 = {v00, v01}, o1 = {v10, v11};
                *(float2*)(C + (size_t)r * Ntot + col) = o0;
                *(float2*)(C + (size_t)(r + 8) * Ntot + col) = o1;
            } else {  // MODE 2: fp16 hi only
                *(__half2*)(Ch + (size_t)r * Ntot + col) =
                    __halves2half2(__float2half_rn(v00), __float2half_rn(v01));
                *(__half2*)(Ch + (size_t)(r + 8) * Ntot + col) =
                    __halves2half2(__float2half_rn(v10), __float2half_rn(v11));
            }
        }
    }
}

// ===================== scores via mma (1-pass): qh @ kh^T ==================
#define RS2 144
#define SC_TILE (128 * RS2)
#define SC_SMEM (2 * SC_TILE)         // 36864: Qh | Kh

__global__ void __launch_bounds__(256, 2)
scores_tc(const float* __restrict__ prev, const float* __restrict__ scale_p,
          float* __restrict__ scores)
{
    extern __shared__ char dsm[];
    const uint32_t sb = smem_u32(dsm);
    const int tid  = threadIdx.x;
    const int lane = tid & 31;
    const int wid  = tid >> 5;
    const int wm   = wid & 3;
    const int wn   = wid >> 2;
    const int bh = blockIdx.z;
    const int b  = bh >> 4;
    const int h  = bh & 15;
    const int q0 = blockIdx.y * 128;
    const int n0 = blockIdx.x * 128;

    const char* pQh = (const char*)g_qh + ((size_t)(b * Sc + q0) * Dc + h * DKc) * 2;
    const char* pKh = (const char*)g_kh + ((size_t)(b * Sc + n0) * Dc + h * DKc) * 2;
    #pragma unroll
    for (int i = 0; i < 4; i++) {
        const int c   = tid + i * 256;
        const int row = c >> 3;
        const int seg = (c & 7) * 16;
        const uint32_t so = (uint32_t)(row * RS2 + seg);
        const size_t go = (size_t)row * (Dc * 2) + seg;
        cp16(sb + so,           pQh + go);
        cp16(sb + SC_TILE + so, pKh + go);
    }
    CP_COMMIT(); CP_WAIT0();
    __syncthreads();

    const uint32_t aRow  = (uint32_t)(wm * 32 + (lane & 15));
    const uint32_t aByte = (uint32_t)((lane >> 4) * 16);
    const uint32_t bRow  = (uint32_t)(wn * 64 + (lane & 7) + ((lane >> 4) & 1) * 8);
    const uint32_t bByte = (uint32_t)(((lane >> 3) & 1) * 16);

    float acc[2][8][4] = {};

    #pragma unroll
    for (int kk = 0; kk < 4; kk++) {
        uint32_t ah[2][4];
        #pragma unroll
        for (int mi = 0; mi < 2; mi++) {
            const uint32_t ad = sb + (aRow + mi * 16) * RS2 + kk * 32 + aByte;
            LDSM4(ah[mi][0], ah[mi][1], ah[mi][2], ah[mi][3], ad);
        }
        #pragma unroll
        for (int hf = 0; hf < 2; hf++) {
            uint32_t bhr[4][2];
            #pragma unroll
            for (int p = 0; p < 2; p++) {
                const uint32_t bd = sb + SC_TILE +
                    (bRow + (hf * 2 + p) * 16) * RS2 + kk * 32 + bByte;
                uint32_t t0, t1, t2, t3;
                LDSM4(t0, t1, t2, t3, bd);
                bhr[2 * p][0] = t0; bhr[2 * p][1] = t1;
                bhr[2 * p + 1][0] = t2; bhr[2 * p + 1][1] = t3;
            }
            #pragma unroll
            for (int mi = 0; mi < 2; mi++)
                #pragma unroll
                for (int nj = 0; nj < 4; nj++)
                    MMA_F16(acc[mi][hf * 4 + nj], ah[mi], bhr[nj]);
        }
    }

    const float scale = *scale_p;
    const int trow = lane >> 2;
    const int tc   = (lane & 3) * 2;
    const size_t base = ((size_t)(b * Hc + h) * Sc) * Sc;
    #pragma unroll
    for (int mi = 0; mi < 2; mi++) {
        const int r = q0 + wm * 32 + mi * 16 + trow;
        #pragma unroll
        for (int ni = 0; ni < 8; ni++) {
            const int col = n0 + wn * 64 + ni * 8 + tc;
            const size_t o0 = base + (size_t)r * Sc + col;
            const size_t o1 = base + (size_t)(r + 8) * Sc + col;
            const float2 p0 = *(const float2*)(prev + o0);
            const float2 p1 = *(const float2*)(prev + o1);
            float2 w0, w1;
            w0.x = fmaf(acc[mi][ni][0], scale, p0.x);
            w0.y = fmaf(acc[mi][ni][1], scale, p0.y);
            w1.x = fmaf(acc[mi][ni][2], scale, p1.x);
            w1.y = fmaf(acc[mi][ni][3], scale, p1.y);
            *(float2*)(scores + o0) = w0;
            *(float2*)(scores + o1) = w1;
        }
    }
}

// ===================== softmax * gate (fp16 gate) ==========================
__global__ void __launch_bounds__(256)
softmax_gate_kernel(float* __restrict__ attn, const float* __restrict__ scores)
{
    const int warp = threadIdx.x >> 5;
    const int lane = threadIdx.x & 31;
    const long long row = (long long)blockIdx.x * 8 + warp;

    const float* srow = scores + row * Sc;
    float*       arow = attn   + row * Sc;

    const int b  = (int)(row >> 13);
    const int hq = (int)(row & 8191);
    const int h  = hq >> 9;
    const int q  = hq & 511;
    const __half* grow = g_gt + (size_t)(b * Sc + q) * Gc + (size_t)h * Sc;

    float4 x[4];
    float mx = -3.402823466e38f;
    #pragma unroll
    for (int t = 0; t < 4; t++) {
        x[t] = *(const float4*)(srow + t * 128 + lane * 4);
        mx = fmaxf(mx, fmaxf(fmaxf(x[t].x, x[t].y), fmaxf(x[t].z, x[t].w)));
    }
    #pragma unroll
    for (int o = 16; o > 0; o >>= 1)
        mx = fmaxf(mx, __shfl_xor_sync(0xffffffffu, mx, o));

    float sum = 0.0f;
    #pragma unroll
    for (int t = 0; t < 4; t++) {
        x[t].x = __expf(x[t].x - mx);
        x[t].y = __expf(x[t].y - mx);
        x[t].z = __expf(x[t].z - mx);
        x[t].w = __expf(x[t].w - mx);
        sum += (x[t].x + x[t].y) + (x[t].z + x[t].w);
    }
    #pragma unroll
    for (int o = 16; o > 0; o >>= 1)
        sum += __shfl_xor_sync(0xffffffffu, sum, o);
    const float inv = 1.0f / sum;

    #pragma unroll
    for (int t = 0; t < 4; t++) {
        const __half2* g2 = (const __half2*)(grow + t * 128 + lane * 4);
        const __half2 ga = g2[0];
        const __half2 gb2 = g2[1];
        float4 o;
        o.x = __low2float(ga)  * x[t].x * inv;
        o.y = __high2float(ga) * x[t].y * inv;
        o.z = __low2float(gb2)  * x[t].z * inv;
        o.w = __high2float(gb2) * x[t].w * inv;
        *(float4*)(arow + t * 128 + lane * 4) = o;
    }
}

// ===================== ctx = attn @ v via mma (1-pass, hi-only out) ========
#define CT_A    (128 * RS2)
#define CT_V    (64 * RS2)
#define CT_SMEM (CT_A + CT_V)   // Ah | Vh  (27648)

__global__ void __launch_bounds__(256, 2)
ctx_tc(const float* __restrict__ attn, __half* __restrict__ Ch)
{
    extern __shared__ char dsm[];
    const uint32_t sA = smem_u32(dsm);
    const uint32_t sV = sA + CT_A;
    const int tid  = threadIdx.x;
    const int lane = tid & 31;
    const int wid  = tid >> 5;
    const int wm   = wid & 3;
    const int wn   = wid >> 2;
    const int bh = blockIdx.y;
    const int b  = bh >> 4;
    const int h  = bh & 15;
    const int q0 = blockIdx.x * 128;

    const size_t abase = ((size_t)(b * Hc + h) * Sc + q0) * Sc;
    const char* pVh = (const char*)g_vh + ((size_t)(b * Sc) * Dc + h * DKc) * 2;

    const uint32_t aRow  = (uint32_t)(wm * 32 + (lane & 15));
    const uint32_t aByte = (uint32_t)((lane >> 4) * 16);
    const uint32_t vRowL = (uint32_t)(lane & 15);
    const uint32_t vColB = (uint32_t)((wn * 32 + (lane >> 4) * 8) * 2);

    float acc[2][4][4] = {};

    for (int kt = 0; kt < 8; kt++) {
        __syncthreads();
        #pragma unroll
        for (int i = 0; i < 2; i++) {
            const int c   = tid + i * 256;
            const int row = c >> 3;
            const int seg = (c & 7) * 16;
            const uint32_t so = (uint32_t)(row * RS2 + seg);
            const size_t go = (size_t)(kt * 64 + row) * (Dc * 2) + seg;
            cp16(sV + so, pVh + go);
        }
        CP_COMMIT();
        // attn tile: 128 rows x 64 fp32 -> fp16 hi in smem
        #pragma unroll
        for (int i = 0; i < 8; i++) {
            const int c   = tid + i * 256;
            const int row = c >> 4;
            const int f4  = c & 15;
            const float4 v = *(const float4*)(attn + abase + (size_t)row * Sc + kt * 64 + f4 * 4);
            const __half2 ph0 = __halves2half2(__float2half_rn(v.x), __float2half_rn(v.y));
            const __half2 ph1 = __halves2half2(__float2half_rn(v.z), __float2half_rn(v.w));
            const uint32_t so = (uint32_t)(row * RS2 + f4 * 8);
            *(uint32_t*)(dsm + (so))     = *(const uint32_t*)&ph0;
            *(uint32_t*)(dsm + (so + 4)) = *(const uint32_t*)&ph1;
        }
        CP_WAIT0();
        __syncthreads();

        #pragma unroll
        for (int kk = 0; kk < 4; kk++) {
            uint32_t ah[2][4];
            #pragma unroll
            for (int mi = 0; mi < 2; mi++) {
                const uint32_t ad = sA + (aRow + mi * 16) * RS2 + kk * 32 + aByte;
                LDSM4(ah[mi][0], ah[mi][1], ah[mi][2], ah[mi][3], ad);
            }
            uint32_t bh_[4][2];
            #pragma unroll
            for (int p = 0; p < 2; p++) {
                const uint32_t vd = sV + (kk * 16 + vRowL) * RS2 + vColB + p * 32;
                uint32_t t0, t1, t2, t3;
                LDSM4T(t0, t1, t2, t3, vd);
                bh_[2 * p][0] = t0; bh_[2 * p][1] = t1;
                bh_[2 * p + 1][0] = t2; bh_[2 * p + 1][1] = t3;
            }
            #pragma unroll
            for (int mi = 0; mi < 2; mi++)
                #pragma unroll
                for (int nj = 0; nj < 4; nj++)
                    MMA_F16(acc[mi][nj], ah[mi], bh_[nj]);
        }
    }

    const int trow = lane >> 2;
    const int tc   = (lane & 3) * 2;
    #pragma unroll
    for (int mi = 0; mi < 2; mi++) {
        const int r = b * Sc + q0 + wm * 32 + mi * 16 + trow;
        #pragma unroll
        for (int nj = 0; nj < 4; nj++) {
            const int col = h * DKc + wn * 32 + nj * 8 + tc;
            *(__half2*)(Ch + (size_t)r * Dc + col) = __halves2half2(
                __float2half_rn(acc[mi][nj][0]), __float2half_rn(acc[mi][nj][1]));
            *(__half2*)(Ch + (size_t)(r + 8) * Dc + col) = __halves2half2(
                __float2half_rn(acc[mi][nj][2]), __float2half_rn(acc[mi][nj][3]));
        }
    }
}

// ---------------------------------------------------------------------------
extern "C" void kernel_launch(void* const* d_in, const int* in_sizes, int n_in,
                              void* d_out, int out_size)
{
    (void)in_sizes; (void)n_in; (void)out_size;

    const float* Q     = (const float*)d_in[0];
    const float* prev  = (const float*)d_in[1];
    const float* Wq    = (const float*)d_in[2];
    const float* bq    = (const float*)d_in[3];
    const float* Wk    = (const float*)d_in[4];
    const float* bk    = (const float*)d_in[5];
    const float* Wv    = (const float*)d_in[6];
    const float* bv    = (const float*)d_in[7];
    const float* Wg    = (const float*)d_in[8];
    const float* bg    = (const float*)d_in[9];
    const float* Wo    = (const float*)d_in[10];
    const float* bo    = (const float*)d_in[11];
    const float* scale = (const float*)d_in[12];

    float* out    = (float*)d_out;
    float* attn   = out + OUT_ELEMS;
    float* scores = attn + ATTN_ELEMS;

    __half *gb, *ah, *wh, *qh, *kh, *vh;
    cudaGetSymbolAddress((void**)&gb, g_gt);
    cudaGetSymbolAddress((void**)&ah, g_ah);
    cudaGetSymbolAddress((void**)&wh, g_wh);
    cudaGetSymbolAddress((void**)&qh, g_qh);
    cudaGetSymbolAddress((void**)&kh, g_kh);
    cudaGetSymbolAddress((void**)&vh, g_vh);

    cudaFuncSetAttribute((const void*)gemm_mma<2>, cudaFuncAttributeMaxDynamicSharedMemorySize, GEMM_SMEM);
    cudaFuncSetAttribute((const void*)gemm_mma<0>, cudaFuncAttributeMaxDynamicSharedMemorySize, GEMM_SMEM);
    cudaFuncSetAttribute((const void*)scores_tc,   cudaFuncAttributeMaxDynamicSharedMemorySize, SC_SMEM);
    cudaFuncSetAttribute((const void*)ctx_tc,      cudaFuncAttributeMaxDynamicSharedMemorySize, CT_SMEM);

    const dim3 tblk(32, 8);
    const long long nQ4 = (long long)Mc * Dc / 4;

    // input activations -> fp16 hi
    split_hi_kernel<<<(int)(nQ4 / 256), 256>>>(Q, ah, nQ4);

    // q projection -> fp16 hi (1-pass)
    transpose_hi<<<dim3(Dc / 32, Dc / 32), tblk>>>(Wq, wh, Dc, Dc);
    gemm_mma<2><<<dim3(Dc / 128, Mc / 128), 256, GEMM_SMEM>>>(ah, wh, bq, nullptr, qh, Dc, Dc);
    // k projection -> fp16 hi (1-pass)
    transpose_hi<<<dim3(Dc / 32, Dc / 32), tblk>>>(Wk, wh, Dc, Dc);
    gemm_mma<2><<<dim3(Dc / 128, Mc / 128), 256, GEMM_SMEM>>>(ah, wh, bk, nullptr, kh, Dc, Dc);
    // v projection -> fp16 hi (1-pass)
    transpose_hi<<<dim3(Dc / 32, Dc / 32), tblk>>>(Wv, wh, Dc, Dc);
    gemm_mma<2><<<dim3(Dc / 128, Mc / 128), 256, GEMM_SMEM>>>(ah, wh, bv, nullptr, vh, Dc, Dc);
    // gate projection (N = 8192) -> fp16 (1-pass)
    transpose_hi<<<dim3(Gc / 32, Dc / 32), tblk>>>(Wg, wh, Dc, Gc);
    gemm_mma<2><<<dim3(Gc / 128, Mc / 128), 256, GEMM_SMEM>>>(ah, wh, bg, nullptr, gb, Gc, Dc);

    // scores = qh kh^T * scale + prev (1-pass)
    scores_tc<<<dim3(4, 4, Bc * Hc), 256, SC_SMEM>>>(prev, scale, scores);
    // attn = gate * softmax(scores)
    softmax_gate_kernel<<<(Bc * Hc * Sc) / 8, 256>>>(attn, scores);
    // ctx = attn @ v (1-pass) -> fp16 hi into ah
    ctx_tc<<<dim3(4, Bc * Hc), 256, CT_SMEM>>>(attn, ah);

    // out = ctx @ Wo + bo (1-pass)
    transpose_hi<<<dim3(Dc / 32, Dc / 32), tblk>>>(Wo, wh, Dc, Dc);
    gemm_mma<0><<<dim3(Dc / 128, Mc / 128), 256, GEMM_SMEM>>>(ah, wh, bo, out, nullptr, Dc, Dc);
}